// round 2
// baseline (speedup 1.0000x reference)
#include <cuda_runtime.h>
#include <cuda_bf16.h>
#include <math.h>

// Problem constants (fixed shapes)
#define Bb 2
#define Ll 2048
#define Dd 1024
#define Hh 16
#define Ee 64
#define TD 3072          // 3*D
#define Mrows 4096       // B*L

// Scratch (device globals — no allocation allowed)
__device__ float g_qkv[(size_t)Mrows * TD];   // feature-mapped q,k and raw v
__device__ float g_attn[(size_t)Mrows * Dd];  // attention output (pre out-proj)

// ---------------------------------------------------------------------------
// GEMM: C[M,N] = A[M,K] @ W[N,K]^T + bias, K = 1024, M = 4096.
// QKV=true: A = Ap (x), C = g_qkv, epilogue applies feature maps.
// QKV=false: A = g_attn, C = Cp (d_out), plain bias epilogue.
// 128x128 tile, BK=16, 256 threads, 8x8 per-thread microtile.
// ---------------------------------------------------------------------------
template<int N, bool QKV>
__global__ __launch_bounds__(256)
void sgemm_tn(const float* __restrict__ Ap, const float* __restrict__ W,
              const float* __restrict__ bias, float* __restrict__ Cp)
{
    constexpr int K = 1024;
    constexpr int BM = 128, BN = 128, BK = 16;
    const float* A = QKV ? Ap : g_attn;
    float*       C = QKV ? g_qkv : Cp;

    __shared__ float As[BK][BM + 4];
    __shared__ float Bs[BK][BN + 4];

    const int tid = threadIdx.x;
    const int m0 = blockIdx.y * BM;
    const int n0 = blockIdx.x * BN;
    const int tm = tid >> 4;          // 0..15
    const int tn = tid & 15;          // 0..15
    const int lr = tid >> 2;          // 0..63
    const int lk = (tid & 3) * 4;     // 0,4,8,12

    float acc[8][8];
    #pragma unroll
    for (int i = 0; i < 8; i++)
        #pragma unroll
        for (int j = 0; j < 8; j++) acc[i][j] = 0.f;

    for (int kt = 0; kt < K; kt += BK) {
        #pragma unroll
        for (int ld = 0; ld < 2; ld++) {
            const int r = lr + ld * 64;
            float4 av = *(const float4*)(A + (size_t)(m0 + r) * K + kt + lk);
            As[lk + 0][r] = av.x; As[lk + 1][r] = av.y;
            As[lk + 2][r] = av.z; As[lk + 3][r] = av.w;
            float4 bv = *(const float4*)(W + (size_t)(n0 + r) * K + kt + lk);
            Bs[lk + 0][r] = bv.x; Bs[lk + 1][r] = bv.y;
            Bs[lk + 2][r] = bv.z; Bs[lk + 3][r] = bv.w;
        }
        __syncthreads();

        #pragma unroll
        for (int kk = 0; kk < BK; kk++) {
            float a[8], b[8];
            *(float4*)&a[0] = *(const float4*)&As[kk][tm * 8];
            *(float4*)&a[4] = *(const float4*)&As[kk][tm * 8 + 4];
            *(float4*)&b[0] = *(const float4*)&Bs[kk][tn * 8];
            *(float4*)&b[4] = *(const float4*)&Bs[kk][tn * 8 + 4];
            #pragma unroll
            for (int i = 0; i < 8; i++)
                #pragma unroll
                for (int j = 0; j < 8; j++)
                    acc[i][j] = fmaf(a[i], b[j], acc[i][j]);
        }
        __syncthreads();
    }

    // Epilogue
    #pragma unroll
    for (int i = 0; i < 8; i++) {
        const int m = m0 + tm * 8 + i;
        #pragma unroll
        for (int j = 0; j < 8; j++) {
            const int n = n0 + tn * 8 + j;
            float v = acc[i][j] + bias[n];
            if (QKV) {
                if (n < 2 * Dd) {  // q or k: elu(v)+1+1e-4
                    float e = v > 0.f ? v : (expf(v) - 1.f);
                    v = e + 1.0001f;
                    if (n < Dd) v *= 0.125f;   // q / sqrt(E), E=64
                }
            }
            C[(size_t)m * N + n] = v;
        }
    }
}

// ---------------------------------------------------------------------------
// Causal linear attention scan.
// Grid: (B*H)*FSPLIT = 128 blocks, 64 threads each.
// Block handles (b,h) and a 16-wide slice of the 64 V-feature columns.
// Thread (fl, g): fl = tid>>2 owns output column fbase+fl; g = tid&3 owns
// rows e in [g*16, g*16+16) of the KV state (16 regs). Per step:
//   S[e][f] += k[e]*v[f]; num[f] = sum_e q[e]*S[e][f] (quad shfl-reduce).
// Denominator: lanes 0..7 of each warp track z-cumsum for 4 e's each
// (warp w covers e in [w*32, w*32+32)), shfl-reduced, combined via smem.
// ---------------------------------------------------------------------------
__global__ __launch_bounds__(64)
void linear_attn_scan()
{
    constexpr int CH = 8;
    const int bh = blockIdx.x >> 2;       // 0..31
    const int fs = blockIdx.x & 3;        // f-split index
    const int b  = bh >> 4;
    const int h  = bh & 15;
    const int fbase = fs * 16;

    const int tid  = threadIdx.x;
    const int fl   = tid >> 2;            // 0..15
    const int g    = tid & 3;             // 0..3
    const int lane = tid & 31;
    const int w    = tid >> 5;            // warp 0/1
    const int ge   = g * 16;
    const bool denp = (lane < 8);
    const int ebase_d = w * 32 + lane * 4;  // valid when denp

    const float* qp = g_qkv + (size_t)(b * Ll) * TD + h * Ee;
    const float* kp = qp + Dd;
    const float* vp = qp + 2 * Dd + fbase;
    float* op = g_attn + (size_t)(b * Ll) * Dd + h * Ee + fbase;

    __shared__ float sq[CH][Ee];
    __shared__ float sk[CH][Ee];
    __shared__ float sv[CH][16];
    __shared__ float sdp[CH][2];

    float S[16];
    #pragma unroll
    for (int i = 0; i < 16; i++) S[i] = 0.f;
    float z[4] = {0.f, 0.f, 0.f, 0.f};

    for (int c0 = 0; c0 < Ll; c0 += CH) {
        // load chunk of q,k (full 64-wide) and v (16-wide slice)
        #pragma unroll
        for (int s = 0; s < CH; s++) {
            sq[s][tid] = qp[(size_t)s * TD + tid];
            sk[s][tid] = kp[(size_t)s * TD + tid];
        }
        #pragma unroll
        for (int it = 0; it < 2; it++) {
            int idx = tid + it * 64;       // 0..127
            int s = idx >> 4, fe = idx & 15;
            sv[s][fe] = vp[(size_t)s * TD + fe];
        }
        __syncthreads();

        float np[CH];
        #pragma unroll
        for (int s = 0; s < CH; s++) {
            const float vf = sv[s][fl];
            float a0 = 0.f, a1 = 0.f;
            #pragma unroll
            for (int i = 0; i < 16; i += 2) {
                float k0 = sk[s][ge + i];
                float k1 = sk[s][ge + i + 1];
                S[i]     = fmaf(k0, vf, S[i]);
                a0       = fmaf(sq[s][ge + i], S[i], a0);
                S[i + 1] = fmaf(k1, vf, S[i + 1]);
                a1       = fmaf(sq[s][ge + i + 1], S[i + 1], a1);
            }
            float npv = a0 + a1;
            npv += __shfl_xor_sync(0xffffffffu, npv, 1);
            npv += __shfl_xor_sync(0xffffffffu, npv, 2);
            np[s] = npv;

            float dp = 0.f;
            if (denp) {
                #pragma unroll
                for (int j = 0; j < 4; j++) {
                    z[j] += sk[s][ebase_d + j];
                    dp = fmaf(sq[s][ebase_d + j], z[j], dp);
                }
            }
            dp += __shfl_xor_sync(0xffffffffu, dp, 1);
            dp += __shfl_xor_sync(0xffffffffu, dp, 2);
            dp += __shfl_xor_sync(0xffffffffu, dp, 4);
            if (lane == 0) sdp[s][w] = dp;
        }
        __syncthreads();

        if (g == 0) {
            #pragma unroll
            for (int s = 0; s < CH; s++) {
                float den = sdp[s][0] + sdp[s][1] + 1e-4f;
                op[(size_t)s * Dd + fl] = np[s] / den;
            }
        }
        // No extra barrier needed: writers read sdp before reaching the next
        // sync; sq/sk/sv rewrites are fenced by the next __syncthreads().
        qp += (size_t)CH * TD;
        kp += (size_t)CH * TD;
        vp += (size_t)CH * TD;
        op += (size_t)CH * Dd;
    }
}

// ---------------------------------------------------------------------------
// In-place LayerNorm over rows of d_out (4096 rows x 1024).
// ---------------------------------------------------------------------------
__global__ __launch_bounds__(256)
void layernorm_inplace(float* __restrict__ out,
                       const float* __restrict__ gamma,
                       const float* __restrict__ beta)
{
    const int row = blockIdx.x;
    float* p = out + (size_t)row * Dd;
    const int tid = threadIdx.x;

    float4 v = ((const float4*)p)[tid];
    float s = v.x + v.y + v.z + v.w;
    float q = v.x * v.x + v.y * v.y + v.z * v.z + v.w * v.w;

    #pragma unroll
    for (int o = 16; o > 0; o >>= 1) {
        s += __shfl_xor_sync(0xffffffffu, s, o);
        q += __shfl_xor_sync(0xffffffffu, q, o);
    }
    __shared__ float ss[8], sqr[8];
    const int w = tid >> 5, lane = tid & 31;
    if (lane == 0) { ss[w] = s; sqr[w] = q; }
    __syncthreads();
    if (w == 0) {
        s = (lane < 8) ? ss[lane] : 0.f;
        q = (lane < 8) ? sqr[lane] : 0.f;
        #pragma unroll
        for (int o = 4; o > 0; o >>= 1) {
            s += __shfl_xor_sync(0xffffffffu, s, o);
            q += __shfl_xor_sync(0xffffffffu, q, o);
        }
        if (lane == 0) { ss[0] = s; sqr[0] = q; }
    }
    __syncthreads();

    const float mu  = ss[0] * (1.f / 1024.f);
    const float var = sqr[0] * (1.f / 1024.f) - mu * mu;
    const float inv = rsqrtf(var + 1e-5f);

    float4 gv = ((const float4*)gamma)[tid];
    float4 bv = ((const float4*)beta)[tid];
    float4 o4;
    o4.x = (v.x - mu) * inv * gv.x + bv.x;
    o4.y = (v.y - mu) * inv * gv.y + bv.y;
    o4.z = (v.z - mu) * inv * gv.z + bv.z;
    o4.w = (v.w - mu) * inv * gv.w + bv.w;
    ((float4*)p)[tid] = o4;
}

// ---------------------------------------------------------------------------
extern "C" void kernel_launch(void* const* d_in, const int* in_sizes, int n_in,
                              void* d_out, int out_size)
{
    const float* x     = (const float*)d_in[0];
    const float* Wqkv  = (const float*)d_in[1];
    const float* bqkv  = (const float*)d_in[2];
    const float* Wout  = (const float*)d_in[3];
    const float* bout  = (const float*)d_in[4];
    const float* gamma = (const float*)d_in[5];
    const float* beta  = (const float*)d_in[6];
    float* out = (float*)d_out;

    // 1) QKV projection + bias + fused feature maps -> g_qkv
    sgemm_tn<TD, true><<<dim3(TD / 128, Mrows / 128), 256>>>(x, Wqkv, bqkv, nullptr);

    // 2) Causal linear attention scan -> g_attn
    linear_attn_scan<<<Bb * Hh * 4, 64>>>();

    // 3) Output projection + bias -> d_out (pre-LN)
    sgemm_tn<Dd, false><<<dim3(Dd / 128, Mrows / 128), 256>>>(nullptr, Wout, bout, out);

    // 4) LayerNorm in place on d_out
    layernorm_inplace<<<Mrows, 256>>>(out, gamma, beta);
}

// round 6
// speedup vs baseline: 1.4039x; 1.4039x over previous
#include <cuda_runtime.h>
#include <cuda_bf16.h>
#include <math.h>
#include <stdint.h>

// Problem constants (fixed shapes)
#define Bb 2
#define Ll 2048
#define Dd 1024
#define Hh 16
#define Ee 64
#define TD 3072          // 3*D
#define Mrows 4096       // B*L
#define Kdim 1024

// ---------------------------------------------------------------------------
// Device scratch (no allocation allowed)
// ---------------------------------------------------------------------------
__device__ float g_qkv[(size_t)Mrows * TD];    // feature-mapped q,k and raw v (fp32)
__device__ float g_attn[(size_t)Mrows * Dd];   // attention output (fp32)

// bf16 hi/lo splits
__device__ __nv_bfloat16 g_xh[(size_t)Mrows * Kdim];
__device__ __nv_bfloat16 g_xl[(size_t)Mrows * Kdim];
__device__ __nv_bfloat16 g_wqh[(size_t)TD * Kdim];
__device__ __nv_bfloat16 g_wql[(size_t)TD * Kdim];
__device__ __nv_bfloat16 g_woh[(size_t)Dd * Kdim];
__device__ __nv_bfloat16 g_wol[(size_t)Dd * Kdim];
__device__ __nv_bfloat16 g_ah[(size_t)Mrows * Kdim];
__device__ __nv_bfloat16 g_al[(size_t)Mrows * Kdim];

// ---------------------------------------------------------------------------
// PTX helpers (base sm_100 feature set: mma.sync, ldmatrix, cp.async)
// ---------------------------------------------------------------------------
__device__ __forceinline__ uint32_t smem_u32(const void* p) {
    uint32_t a;
    asm("{ .reg .u64 t; cvta.to.shared.u64 t, %1; cvt.u32.u64 %0, t; }" : "=r"(a) : "l"(p));
    return a;
}

#define CP16(dst, src) \
    asm volatile("cp.async.cg.shared.global [%0], [%1], 16;" :: "r"(dst), "l"(src))
#define CP_COMMIT() asm volatile("cp.async.commit_group;" ::: "memory")
#define CP_WAIT1()  asm volatile("cp.async.wait_group 1;" ::: "memory")
#define CP_WAIT0()  asm volatile("cp.async.wait_group 0;" ::: "memory")

#define LDSM4(r0, r1, r2, r3, addr) \
    asm volatile("ldmatrix.sync.aligned.m8n8.x4.shared.b16 {%0,%1,%2,%3}, [%4];" \
        : "=r"(r0), "=r"(r1), "=r"(r2), "=r"(r3) : "r"(addr))

#define MMA(d, a, b) \
    asm volatile("mma.sync.aligned.m16n8k16.row.col.f32.bf16.bf16.f32 " \
        "{%0,%1,%2,%3},{%4,%5,%6,%7},{%8,%9},{%0,%1,%2,%3};" \
        : "+f"((d)[0]), "+f"((d)[1]), "+f"((d)[2]), "+f"((d)[3]) \
        : "r"((a)[0]), "r"((a)[1]), "r"((a)[2]), "r"((a)[3]), \
          "r"((b)[0]), "r"((b)[1]))

// ---------------------------------------------------------------------------
// bf16 split: hi = bf16(x), lo = bf16(x - hi)
// ---------------------------------------------------------------------------
__global__ __launch_bounds__(256)
void split_bf16(const float* __restrict__ s, __nv_bfloat16* __restrict__ h,
                __nv_bfloat16* __restrict__ l, int n4) {
    int i = blockIdx.x * 256 + threadIdx.x;
    if (i >= n4) return;
    float4 v = ((const float4*)s)[i];
    __nv_bfloat16 h0 = __float2bfloat16_rn(v.x);
    __nv_bfloat16 h1 = __float2bfloat16_rn(v.y);
    __nv_bfloat16 h2 = __float2bfloat16_rn(v.z);
    __nv_bfloat16 h3 = __float2bfloat16_rn(v.w);
    __nv_bfloat16 l0 = __float2bfloat16_rn(v.x - __bfloat162float(h0));
    __nv_bfloat16 l1 = __float2bfloat16_rn(v.y - __bfloat162float(h1));
    __nv_bfloat16 l2 = __float2bfloat16_rn(v.z - __bfloat162float(h2));
    __nv_bfloat16 l3 = __float2bfloat16_rn(v.w - __bfloat162float(h3));
    ((__nv_bfloat162*)h)[2 * i]     = __nv_bfloat162(h0, h1);
    ((__nv_bfloat162*)h)[2 * i + 1] = __nv_bfloat162(h2, h3);
    ((__nv_bfloat162*)l)[2 * i]     = __nv_bfloat162(l0, l1);
    ((__nv_bfloat162*)l)[2 * i + 1] = __nv_bfloat162(l2, l3);
}

// ---------------------------------------------------------------------------
// mma.sync GEMM: C[M,N] = (Ah+Al)[M,K] @ (Bh+Bl)[N,K]^T + bias  (3-term split)
// 128x128x32 tile, 256 threads (8 warps as 2m x 4n, warp tile 64x32),
// double-buffered cp.async, padded smem (80B row pitch: 16B-aligned AND
// conflict-free for ldmatrix: 8-row start banks {0,20,8,28,16,4,24,12}).
// ---------------------------------------------------------------------------
#define TPITCH 80                 // bytes per 32-halves row (64B + 16B pad)
#define TSZ   (128 * TPITCH)      // one tile: 10240 B
#define GSM   (2 * 4 * TSZ)       // 2 buffers x 4 tiles = 81920 B

template<bool QKV>
__global__ __launch_bounds__(256)
void mma_gemm(const float* __restrict__ bias, float* __restrict__ Cp)
{
    constexpr int NTOT = QKV ? TD : Dd;
    extern __shared__ char sm[];
    const uint32_t sb = smem_u32(sm);

    const __nv_bfloat16* Ahp = QKV ? g_xh : g_ah;
    const __nv_bfloat16* Alp = QKV ? g_xl : g_al;
    const __nv_bfloat16* Bhp = QKV ? g_wqh : g_woh;
    const __nv_bfloat16* Blp = QKV ? g_wql : g_wol;
    float* C = QKV ? g_qkv : Cp;

    const int tid  = threadIdx.x;
    const int lane = tid & 31;
    const int wid  = tid >> 5;
    const int wm   = wid & 1;         // 0..1 (m direction, 64 rows each)
    const int wn   = wid >> 1;        // 0..3 (n direction, 32 cols each)
    const int m0   = blockIdx.y * 128;
    const int n0   = blockIdx.x * 128;

    // per-thread cp.async coords: 4 chunks/row-half, 2 row-halves
    const int lrow = tid >> 2;            // 0..63
    const int lcb  = (tid & 3) * 16;      // byte col in smem row
    const int lce  = (tid & 3) * 8;       // element col in gmem row

    const __nv_bfloat16* gsrc[4] = {
        Ahp + (size_t)m0 * Kdim, Alp + (size_t)m0 * Kdim,
        Bhp + (size_t)n0 * Kdim, Blp + (size_t)n0 * Kdim };

    float acc[4][4][4];
    #pragma unroll
    for (int i = 0; i < 4; i++)
        #pragma unroll
        for (int j = 0; j < 4; j++)
            #pragma unroll
            for (int r = 0; r < 4; r++) acc[i][j][r] = 0.f;

    // ---- async tile loader ----
    #define ISSUE(buf, kc) do {                                               \
        const int k0_ = (kc) * 32;                                            \
        const uint32_t db_ = sb + (buf) * 4 * TSZ;                            \
        _Pragma("unroll")                                                     \
        for (int t_ = 0; t_ < 4; t_++) {                                      \
            const __nv_bfloat16* bp_ = gsrc[t_];                              \
            uint32_t ds_ = db_ + t_ * TSZ;                                    \
            CP16(ds_ + lrow * TPITCH + lcb,                                   \
                 bp_ + (size_t)lrow * Kdim + k0_ + lce);                      \
            CP16(ds_ + (lrow + 64) * TPITCH + lcb,                            \
                 bp_ + (size_t)(lrow + 64) * Kdim + k0_ + lce);               \
        }                                                                     \
    } while (0)

    ISSUE(0, 0); CP_COMMIT();

    const int r16 = lane & 15;
    const int kb8 = (lane >> 4) * 16;     // byte offset of 8-half group

    int buf = 0;
    for (int kc = 0; kc < Kdim / 32; kc++) {
        if (kc + 1 < Kdim / 32) { ISSUE(buf ^ 1, kc + 1); CP_COMMIT(); CP_WAIT1(); }
        else                    { CP_WAIT0(); }
        __syncthreads();

        const uint32_t base = sb + buf * 4 * TSZ;
        const uint32_t sAh = base, sAl = base + TSZ;
        const uint32_t sBh = base + 2 * TSZ, sBl = base + 3 * TSZ;

        #pragma unroll
        for (int ks = 0; ks < 2; ks++) {
            const int kbyte = ks * 32 + kb8;
            uint32_t ah[4][4], al[4][4], bh[4][2], bl[4][2];
            #pragma unroll
            for (int tm = 0; tm < 4; tm++) {
                const uint32_t roff = (uint32_t)(wm * 64 + tm * 16 + r16) * TPITCH + kbyte;
                LDSM4(ah[tm][0], ah[tm][1], ah[tm][2], ah[tm][3], sAh + roff);
                LDSM4(al[tm][0], al[tm][1], al[tm][2], al[tm][3], sAl + roff);
            }
            #pragma unroll
            for (int tp = 0; tp < 2; tp++) {
                const uint32_t roff = (uint32_t)(wn * 32 + tp * 16 + r16) * TPITCH + kbyte;
                uint32_t r0, r1, r2, r3;
                LDSM4(r0, r1, r2, r3, sBh + roff);
                bh[tp * 2][0] = r0; bh[tp * 2 + 1][0] = r1;
                bh[tp * 2][1] = r2; bh[tp * 2 + 1][1] = r3;
                LDSM4(r0, r1, r2, r3, sBl + roff);
                bl[tp * 2][0] = r0; bl[tp * 2 + 1][0] = r1;
                bl[tp * 2][1] = r2; bl[tp * 2 + 1][1] = r3;
            }
            #pragma unroll
            for (int tm = 0; tm < 4; tm++)
                #pragma unroll
                for (int tn = 0; tn < 4; tn++) {
                    MMA(acc[tm][tn], ah[tm], bh[tn]);
                    MMA(acc[tm][tn], ah[tm], bl[tn]);
                    MMA(acc[tm][tn], al[tm], bh[tn]);
                }
        }
        __syncthreads();
        buf ^= 1;
    }
    #undef ISSUE

    // ---- epilogue: bias + (QKV) feature maps, direct global stores ----
    #pragma unroll
    for (int tm = 0; tm < 4; tm++) {
        const int row = m0 + wm * 64 + tm * 16 + (lane >> 2);
        #pragma unroll
        for (int tn = 0; tn < 4; tn++) {
            const int col = n0 + wn * 32 + tn * 8 + (lane & 3) * 2;
            #pragma unroll
            for (int half = 0; half < 2; half++) {
                const int m = row + half * 8;
                float v0 = acc[tm][tn][half * 2 + 0] + bias[col];
                float v1 = acc[tm][tn][half * 2 + 1] + bias[col + 1];
                if (QKV) {
                    if (col < 2 * Dd) {
                        float e0 = v0 > 0.f ? v0 : (expf(v0) - 1.f);
                        float e1 = v1 > 0.f ? v1 : (expf(v1) - 1.f);
                        v0 = e0 + 1.0001f; v1 = e1 + 1.0001f;
                        if (col < Dd) { v0 *= 0.125f; v1 *= 0.125f; }
                    }
                }
                float2 o; o.x = v0; o.y = v1;
                *(float2*)(C + (size_t)m * NTOT + col) = o;
            }
        }
    }
}

// ---------------------------------------------------------------------------
// Causal linear attention scan (unchanged from passing R2 version).
// ---------------------------------------------------------------------------
__global__ __launch_bounds__(64)
void linear_attn_scan()
{
    constexpr int CH = 8;
    const int bh = blockIdx.x >> 2;
    const int fs = blockIdx.x & 3;
    const int b  = bh >> 4;
    const int h  = bh & 15;
    const int fbase = fs * 16;

    const int tid  = threadIdx.x;
    const int fl   = tid >> 2;
    const int g    = tid & 3;
    const int lane = tid & 31;
    const int w    = tid >> 5;
    const int ge   = g * 16;
    const bool denp = (lane < 8);
    const int ebase_d = w * 32 + lane * 4;

    const float* qp = g_qkv + (size_t)(b * Ll) * TD + h * Ee;
    const float* kp = qp + Dd;
    const float* vp = qp + 2 * Dd + fbase;
    float* op = g_attn + (size_t)(b * Ll) * Dd + h * Ee + fbase;

    __shared__ float sq[CH][Ee];
    __shared__ float sk[CH][Ee];
    __shared__ float sv[CH][16];
    __shared__ float sdp[CH][2];

    float S[16];
    #pragma unroll
    for (int i = 0; i < 16; i++) S[i] = 0.f;
    float z[4] = {0.f, 0.f, 0.f, 0.f};

    for (int c0 = 0; c0 < Ll; c0 += CH) {
        #pragma unroll
        for (int s = 0; s < CH; s++) {
            sq[s][tid] = qp[(size_t)s * TD + tid];
            sk[s][tid] = kp[(size_t)s * TD + tid];
        }
        #pragma unroll
        for (int it = 0; it < 2; it++) {
            int idx = tid + it * 64;
            int s = idx >> 4, fe = idx & 15;
            sv[s][fe] = vp[(size_t)s * TD + fe];
        }
        __syncthreads();

        float np[CH];
        #pragma unroll
        for (int s = 0; s < CH; s++) {
            const float vf = sv[s][fl];
            float a0 = 0.f, a1 = 0.f;
            #pragma unroll
            for (int i = 0; i < 16; i += 2) {
                float k0 = sk[s][ge + i];
                float k1 = sk[s][ge + i + 1];
                S[i]     = fmaf(k0, vf, S[i]);
                a0       = fmaf(sq[s][ge + i], S[i], a0);
                S[i + 1] = fmaf(k1, vf, S[i + 1]);
                a1       = fmaf(sq[s][ge + i + 1], S[i + 1], a1);
            }
            float npv = a0 + a1;
            npv += __shfl_xor_sync(0xffffffffu, npv, 1);
            npv += __shfl_xor_sync(0xffffffffu, npv, 2);
            np[s] = npv;

            float dp = 0.f;
            if (denp) {
                #pragma unroll
                for (int j = 0; j < 4; j++) {
                    z[j] += sk[s][ebase_d + j];
                    dp = fmaf(sq[s][ebase_d + j], z[j], dp);
                }
            }
            dp += __shfl_xor_sync(0xffffffffu, dp, 1);
            dp += __shfl_xor_sync(0xffffffffu, dp, 2);
            dp += __shfl_xor_sync(0xffffffffu, dp, 4);
            if (lane == 0) sdp[s][w] = dp;
        }
        __syncthreads();

        if (g == 0) {
            #pragma unroll
            for (int s = 0; s < CH; s++) {
                float den = sdp[s][0] + sdp[s][1] + 1e-4f;
                op[(size_t)s * Dd + fl] = np[s] / den;
            }
        }
        qp += (size_t)CH * TD;
        kp += (size_t)CH * TD;
        vp += (size_t)CH * TD;
        op += (size_t)CH * Dd;
    }
}

// ---------------------------------------------------------------------------
// In-place LayerNorm over rows of d_out (4096 rows x 1024).
// ---------------------------------------------------------------------------
__global__ __launch_bounds__(256)
void layernorm_inplace(float* __restrict__ out,
                       const float* __restrict__ gamma,
                       const float* __restrict__ beta)
{
    const int row = blockIdx.x;
    float* p = out + (size_t)row * Dd;
    const int tid = threadIdx.x;

    float4 v = ((const float4*)p)[tid];
    float s = v.x + v.y + v.z + v.w;
    float q = v.x * v.x + v.y * v.y + v.z * v.z + v.w * v.w;

    #pragma unroll
    for (int o = 16; o > 0; o >>= 1) {
        s += __shfl_xor_sync(0xffffffffu, s, o);
        q += __shfl_xor_sync(0xffffffffu, q, o);
    }
    __shared__ float ss[8], sqr[8];
    const int w = tid >> 5, lane = tid & 31;
    if (lane == 0) { ss[w] = s; sqr[w] = q; }
    __syncthreads();
    if (w == 0) {
        s = (lane < 8) ? ss[lane] : 0.f;
        q = (lane < 8) ? sqr[lane] : 0.f;
        #pragma unroll
        for (int o = 4; o > 0; o >>= 1) {
            s += __shfl_xor_sync(0xffffffffu, s, o);
            q += __shfl_xor_sync(0xffffffffu, q, o);
        }
        if (lane == 0) { ss[0] = s; sqr[0] = q; }
    }
    __syncthreads();

    const float mu  = ss[0] * (1.f / 1024.f);
    const float var = sqr[0] * (1.f / 1024.f) - mu * mu;
    const float inv = rsqrtf(var + 1e-5f);

    float4 gv = ((const float4*)gamma)[tid];
    float4 bv = ((const float4*)beta)[tid];
    float4 o4;
    o4.x = (v.x - mu) * inv * gv.x + bv.x;
    o4.y = (v.y - mu) * inv * gv.y + bv.y;
    o4.z = (v.z - mu) * inv * gv.z + bv.z;
    o4.w = (v.w - mu) * inv * gv.w + bv.w;
    ((float4*)p)[tid] = o4;
}

// ---------------------------------------------------------------------------
extern "C" void kernel_launch(void* const* d_in, const int* in_sizes, int n_in,
                              void* d_out, int out_size)
{
    const float* x     = (const float*)d_in[0];
    const float* Wqkv  = (const float*)d_in[1];
    const float* bqkv  = (const float*)d_in[2];
    const float* Wout  = (const float*)d_in[3];
    const float* bout  = (const float*)d_in[4];
    const float* gamma = (const float*)d_in[5];
    const float* beta  = (const float*)d_in[6];
    float* out = (float*)d_out;

    cudaFuncSetAttribute(mma_gemm<true>,  cudaFuncAttributeMaxDynamicSharedMemorySize, GSM);
    cudaFuncSetAttribute(mma_gemm<false>, cudaFuncAttributeMaxDynamicSharedMemorySize, GSM);

    __nv_bfloat16 *xh, *xl, *wqh, *wql, *woh, *wol, *ah, *al;
    cudaGetSymbolAddress((void**)&xh,  g_xh);
    cudaGetSymbolAddress((void**)&xl,  g_xl);
    cudaGetSymbolAddress((void**)&wqh, g_wqh);
    cudaGetSymbolAddress((void**)&wql, g_wql);
    cudaGetSymbolAddress((void**)&woh, g_woh);
    cudaGetSymbolAddress((void**)&wol, g_wol);
    cudaGetSymbolAddress((void**)&ah,  g_ah);
    cudaGetSymbolAddress((void**)&al,  g_al);
    float* attn;
    cudaGetSymbolAddress((void**)&attn, g_attn);

    // 0) bf16 splits of x and weights
    split_bf16<<<(Mrows * Kdim / 4 + 255) / 256, 256>>>(x, xh, xl, Mrows * Kdim / 4);
    split_bf16<<<(TD * Kdim / 4 + 255) / 256, 256>>>(Wqkv, wqh, wql, TD * Kdim / 4);
    split_bf16<<<(Dd * Kdim / 4 + 255) / 256, 256>>>(Wout, woh, wol, Dd * Kdim / 4);

    // 1) QKV projection (mma.sync) + bias + feature maps -> g_qkv
    mma_gemm<true><<<dim3(TD / 128, Mrows / 128), 256, GSM>>>(bqkv, nullptr);

    // 2) Causal linear attention scan -> g_attn
    linear_attn_scan<<<Bb * Hh * 4, 64>>>();

    // 2b) split attention output for the out-proj MMA
    split_bf16<<<(Mrows * Kdim / 4 + 255) / 256, 256>>>(attn, ah, al, Mrows * Kdim / 4);

    // 3) Output projection (mma.sync) + bias -> d_out
    mma_gemm<false><<<dim3(Dd / 128, Mrows / 128), 256, GSM>>>(bout, out);

    // 4) LayerNorm in place on d_out
    layernorm_inplace<<<Mrows, 256>>>(out, gamma, beta);
}

// round 8
// speedup vs baseline: 2.8602x; 2.0372x over previous
#include <cuda_runtime.h>
#include <cuda_bf16.h>
#include <math.h>
#include <stdint.h>

// Problem constants (fixed shapes)
#define Bb 2
#define Ll 2048
#define Dd 1024
#define Hh 16
#define Ee 64
#define TD 3072          // 3*D
#define Mrows 4096       // B*L
#define Kdim 1024
#define CL 128           // chunk length
#define NC 16            // chunks per (b,h) sequence

// ---------------------------------------------------------------------------
// Device scratch (no allocation allowed)
// ---------------------------------------------------------------------------
__device__ float g_qkv[(size_t)Mrows * TD];    // feature-mapped q,k and raw v (fp32)
__device__ float g_attn[(size_t)Mrows * Dd];   // attention output (fp32)
__device__ float g_kv[(size_t)Bb * Hh * NC * Ee * Ee];  // per-chunk KV sums -> exclusive prefixes
__device__ float g_zc[(size_t)Bb * Hh * NC * Ee];       // per-chunk k sums  -> exclusive prefixes

// bf16 hi/lo splits
__device__ __nv_bfloat16 g_xh[(size_t)Mrows * Kdim];
__device__ __nv_bfloat16 g_xl[(size_t)Mrows * Kdim];
__device__ __nv_bfloat16 g_wqh[(size_t)TD * Kdim];
__device__ __nv_bfloat16 g_wql[(size_t)TD * Kdim];
__device__ __nv_bfloat16 g_woh[(size_t)Dd * Kdim];
__device__ __nv_bfloat16 g_wol[(size_t)Dd * Kdim];
__device__ __nv_bfloat16 g_ah[(size_t)Mrows * Kdim];
__device__ __nv_bfloat16 g_al[(size_t)Mrows * Kdim];

// ---------------------------------------------------------------------------
// PTX helpers (base sm_100 feature set: mma.sync, ldmatrix, cp.async)
// ---------------------------------------------------------------------------
__device__ __forceinline__ uint32_t smem_u32(const void* p) {
    uint32_t a;
    asm("{ .reg .u64 t; cvta.to.shared.u64 t, %1; cvt.u32.u64 %0, t; }" : "=r"(a) : "l"(p));
    return a;
}

#define CP16(dst, src) \
    asm volatile("cp.async.cg.shared.global [%0], [%1], 16;" :: "r"(dst), "l"(src))
#define CP_COMMIT() asm volatile("cp.async.commit_group;" ::: "memory")
#define CP_WAIT1()  asm volatile("cp.async.wait_group 1;" ::: "memory")
#define CP_WAIT0()  asm volatile("cp.async.wait_group 0;" ::: "memory")

#define LDSM4(r0, r1, r2, r3, addr) \
    asm volatile("ldmatrix.sync.aligned.m8n8.x4.shared.b16 {%0,%1,%2,%3}, [%4];" \
        : "=r"(r0), "=r"(r1), "=r"(r2), "=r"(r3) : "r"(addr))

#define MMA(d, a, b) \
    asm volatile("mma.sync.aligned.m16n8k16.row.col.f32.bf16.bf16.f32 " \
        "{%0,%1,%2,%3},{%4,%5,%6,%7},{%8,%9},{%0,%1,%2,%3};" \
        : "+f"((d)[0]), "+f"((d)[1]), "+f"((d)[2]), "+f"((d)[3]) \
        : "r"((a)[0]), "r"((a)[1]), "r"((a)[2]), "r"((a)[3]), \
          "r"((b)[0]), "r"((b)[1]))

// ---------------------------------------------------------------------------
// bf16 split: hi = bf16(x), lo = bf16(x - hi)
// ---------------------------------------------------------------------------
__global__ __launch_bounds__(256)
void split_bf16(const float* __restrict__ s, __nv_bfloat16* __restrict__ h,
                __nv_bfloat16* __restrict__ l, int n4) {
    int i = blockIdx.x * 256 + threadIdx.x;
    if (i >= n4) return;
    float4 v = ((const float4*)s)[i];
    __nv_bfloat16 h0 = __float2bfloat16_rn(v.x);
    __nv_bfloat16 h1 = __float2bfloat16_rn(v.y);
    __nv_bfloat16 h2 = __float2bfloat16_rn(v.z);
    __nv_bfloat16 h3 = __float2bfloat16_rn(v.w);
    __nv_bfloat16 l0 = __float2bfloat16_rn(v.x - __bfloat162float(h0));
    __nv_bfloat16 l1 = __float2bfloat16_rn(v.y - __bfloat162float(h1));
    __nv_bfloat16 l2 = __float2bfloat16_rn(v.z - __bfloat162float(h2));
    __nv_bfloat16 l3 = __float2bfloat16_rn(v.w - __bfloat162float(h3));
    ((__nv_bfloat162*)h)[2 * i]     = __nv_bfloat162(h0, h1);
    ((__nv_bfloat162*)h)[2 * i + 1] = __nv_bfloat162(h2, h3);
    ((__nv_bfloat162*)l)[2 * i]     = __nv_bfloat162(l0, l1);
    ((__nv_bfloat162*)l)[2 * i + 1] = __nv_bfloat162(l2, l3);
}

// ---------------------------------------------------------------------------
// mma.sync GEMM (unchanged from passing R6 version).
// ---------------------------------------------------------------------------
#define TPITCH 80
#define TSZ   (128 * TPITCH)
#define GSM   (2 * 4 * TSZ)

template<bool QKV>
__global__ __launch_bounds__(256)
void mma_gemm(const float* __restrict__ bias, float* __restrict__ Cp)
{
    constexpr int NTOT = QKV ? TD : Dd;
    extern __shared__ char sm[];
    const uint32_t sb = smem_u32(sm);

    const __nv_bfloat16* Ahp = QKV ? g_xh : g_ah;
    const __nv_bfloat16* Alp = QKV ? g_xl : g_al;
    const __nv_bfloat16* Bhp = QKV ? g_wqh : g_woh;
    const __nv_bfloat16* Blp = QKV ? g_wql : g_wol;
    float* C = QKV ? g_qkv : Cp;

    const int tid  = threadIdx.x;
    const int lane = tid & 31;
    const int wid  = tid >> 5;
    const int wm   = wid & 1;
    const int wn   = wid >> 1;
    const int m0   = blockIdx.y * 128;
    const int n0   = blockIdx.x * 128;

    const int lrow = tid >> 2;
    const int lcb  = (tid & 3) * 16;
    const int lce  = (tid & 3) * 8;

    const __nv_bfloat16* gsrc[4] = {
        Ahp + (size_t)m0 * Kdim, Alp + (size_t)m0 * Kdim,
        Bhp + (size_t)n0 * Kdim, Blp + (size_t)n0 * Kdim };

    float acc[4][4][4];
    #pragma unroll
    for (int i = 0; i < 4; i++)
        #pragma unroll
        for (int j = 0; j < 4; j++)
            #pragma unroll
            for (int r = 0; r < 4; r++) acc[i][j][r] = 0.f;

    #define ISSUE(buf, kc) do {                                               \
        const int k0_ = (kc) * 32;                                            \
        const uint32_t db_ = sb + (buf) * 4 * TSZ;                            \
        _Pragma("unroll")                                                     \
        for (int t_ = 0; t_ < 4; t_++) {                                      \
            const __nv_bfloat16* bp_ = gsrc[t_];                              \
            uint32_t ds_ = db_ + t_ * TSZ;                                    \
            CP16(ds_ + lrow * TPITCH + lcb,                                   \
                 bp_ + (size_t)lrow * Kdim + k0_ + lce);                      \
            CP16(ds_ + (lrow + 64) * TPITCH + lcb,                            \
                 bp_ + (size_t)(lrow + 64) * Kdim + k0_ + lce);               \
        }                                                                     \
    } while (0)

    ISSUE(0, 0); CP_COMMIT();

    const int r16 = lane & 15;
    const int kb8 = (lane >> 4) * 16;

    int buf = 0;
    for (int kc = 0; kc < Kdim / 32; kc++) {
        if (kc + 1 < Kdim / 32) { ISSUE(buf ^ 1, kc + 1); CP_COMMIT(); CP_WAIT1(); }
        else                    { CP_WAIT0(); }
        __syncthreads();

        const uint32_t base = sb + buf * 4 * TSZ;
        const uint32_t sAh = base, sAl = base + TSZ;
        const uint32_t sBh = base + 2 * TSZ, sBl = base + 3 * TSZ;

        #pragma unroll
        for (int ks = 0; ks < 2; ks++) {
            const int kbyte = ks * 32 + kb8;
            uint32_t ah[4][4], al[4][4], bh[4][2], bl[4][2];
            #pragma unroll
            for (int tm = 0; tm < 4; tm++) {
                const uint32_t roff = (uint32_t)(wm * 64 + tm * 16 + r16) * TPITCH + kbyte;
                LDSM4(ah[tm][0], ah[tm][1], ah[tm][2], ah[tm][3], sAh + roff);
                LDSM4(al[tm][0], al[tm][1], al[tm][2], al[tm][3], sAl + roff);
            }
            #pragma unroll
            for (int tp = 0; tp < 2; tp++) {
                const uint32_t roff = (uint32_t)(wn * 32 + tp * 16 + r16) * TPITCH + kbyte;
                uint32_t r0, r1, r2, r3;
                LDSM4(r0, r1, r2, r3, sBh + roff);
                bh[tp * 2][0] = r0; bh[tp * 2 + 1][0] = r1;
                bh[tp * 2][1] = r2; bh[tp * 2 + 1][1] = r3;
                LDSM4(r0, r1, r2, r3, sBl + roff);
                bl[tp * 2][0] = r0; bl[tp * 2 + 1][0] = r1;
                bl[tp * 2][1] = r2; bl[tp * 2 + 1][1] = r3;
            }
            #pragma unroll
            for (int tm = 0; tm < 4; tm++)
                #pragma unroll
                for (int tn = 0; tn < 4; tn++) {
                    MMA(acc[tm][tn], ah[tm], bh[tn]);
                    MMA(acc[tm][tn], ah[tm], bl[tn]);
                    MMA(acc[tm][tn], al[tm], bh[tn]);
                }
        }
        __syncthreads();
        buf ^= 1;
    }
    #undef ISSUE

    #pragma unroll
    for (int tm = 0; tm < 4; tm++) {
        const int row = m0 + wm * 64 + tm * 16 + (lane >> 2);
        #pragma unroll
        for (int tn = 0; tn < 4; tn++) {
            const int col = n0 + wn * 32 + tn * 8 + (lane & 3) * 2;
            #pragma unroll
            for (int half = 0; half < 2; half++) {
                const int m = row + half * 8;
                float v0 = acc[tm][tn][half * 2 + 0] + bias[col];
                float v1 = acc[tm][tn][half * 2 + 1] + bias[col + 1];
                if (QKV) {
                    if (col < 2 * Dd) {
                        float e0 = v0 > 0.f ? v0 : (expf(v0) - 1.f);
                        float e1 = v1 > 0.f ? v1 : (expf(v1) - 1.f);
                        v0 = e0 + 1.0001f; v1 = e1 + 1.0001f;
                        if (col < Dd) { v0 *= 0.125f; v1 *= 0.125f; }
                    }
                }
                float2 o; o.x = v0; o.y = v1;
                *(float2*)(C + (size_t)m * NTOT + col) = o;
            }
        }
    }
}

// ---------------------------------------------------------------------------
// Chunked linear attention, stage A: per-chunk KV outer-product sums + k sums.
// Grid: Bb*Hh*NC = 512 blocks, 256 threads, 68 KB DYNAMIC smem.
// ---------------------------------------------------------------------------
#define CK_SK 0
#define CK_SV (CL * 68)
#define CK_TOT ((CL * 68 * 2) * 4)     // 69632 bytes

__global__ __launch_bounds__(256)
void chunk_kv()
{
    extern __shared__ float s[];
    float (*sk)[68] = (float(*)[68])(s + CK_SK);
    float (*sv)[68] = (float(*)[68])(s + CK_SV);

    const int blk = blockIdx.x;
    const int bh = blk >> 4, c = blk & 15;
    const int b = bh >> 4, h = bh & 15;
    const float* kbase = g_qkv + ((size_t)(b * Ll + c * CL)) * TD + Dd + h * Ee;
    const float* vbase = kbase + Dd;
    const int tid = threadIdx.x;

    #pragma unroll
    for (int t = 0; t < 8; t++) {
        int id = tid + t * 256;            // 0..2047 = 128 rows x 16 float4
        int i = id >> 4, c4 = (id & 15) * 4;
        *(float4*)&sk[i][c4] = *(const float4*)(kbase + (size_t)i * TD + c4);
        *(float4*)&sv[i][c4] = *(const float4*)(vbase + (size_t)i * TD + c4);
    }
    __syncthreads();

    const int te = tid >> 4, tf = tid & 15;
    const int e0 = te * 4, f0 = tf * 4;
    float acc[4][4] = {};
    float z4[4] = {0.f, 0.f, 0.f, 0.f};

    for (int i = 0; i < CL; i++) {
        float4 k4 = *(float4*)&sk[i][e0];
        float4 v4 = *(float4*)&sv[i][f0];
        float kk[4] = {k4.x, k4.y, k4.z, k4.w};
        float vv[4] = {v4.x, v4.y, v4.z, v4.w};
        #pragma unroll
        for (int r = 0; r < 4; r++) {
            #pragma unroll
            for (int q = 0; q < 4; q++) acc[r][q] = fmaf(kk[r], vv[q], acc[r][q]);
        }
        if (tf == 0) {
            #pragma unroll
            for (int r = 0; r < 4; r++) z4[r] += kk[r];
        }
    }

    float* kvo = g_kv + (size_t)blk * Ee * Ee;
    #pragma unroll
    for (int r = 0; r < 4; r++) {
        float4 o; o.x = acc[r][0]; o.y = acc[r][1]; o.z = acc[r][2]; o.w = acc[r][3];
        *(float4*)&kvo[(e0 + r) * Ee + f0] = o;
    }
    if (tf == 0) {
        float* zo = g_zc + (size_t)blk * Ee;
        #pragma unroll
        for (int r = 0; r < 4; r++) zo[e0 + r] = z4[r];
    }
}

// ---------------------------------------------------------------------------
// Stage B: in-place exclusive prefix over the NC chunks of each (b,h).
// Grid: 32 blocks (one per bh), 256 threads.
// ---------------------------------------------------------------------------
__global__ __launch_bounds__(256)
void prefix_kv()
{
    const int bh = blockIdx.x;
    const int tid = threadIdx.x;
    float* kvb = g_kv + (size_t)bh * NC * Ee * Ee;

    #pragma unroll
    for (int t = 0; t < 16; t++) {
        const int idx = tid + t * 256;
        float run = 0.f;
        #pragma unroll
        for (int c = 0; c < NC; c++) {
            float tmp = kvb[(size_t)c * (Ee * Ee) + idx];
            kvb[(size_t)c * (Ee * Ee) + idx] = run;
            run += tmp;
        }
    }
    if (tid < Ee) {
        float* zb = g_zc + (size_t)bh * NC * Ee;
        float run = 0.f;
        #pragma unroll
        for (int c = 0; c < NC; c++) {
            float tmp = zb[c * Ee + tid];
            zb[c * Ee + tid] = run;
            run += tmp;
        }
    }
}

// ---------------------------------------------------------------------------
// Stage C: per-chunk attention.
//   A = causal-masked Q K^T (intra-chunk), num = A V + Q S_prev,
//   den = rowsum(A) + q . z_prev,  out = num / (den + 1e-4).
// Grid: 512 blocks, 256 threads, ~183 KB dynamic smem.
// ---------------------------------------------------------------------------
#define CA_SQT 0                          // [64][132] Q transposed
#define CA_SKT (64 * 132)                 // [64][132] K transposed
#define CA_SV  (CA_SKT + 64 * 132)        // [128][68] V
#define CA_SA  (CA_SV + 128 * 68)         // [128][132] masked A
#define CA_SSP (CA_SA + 128 * 132)        // [64][68]  S_prev
#define CA_SZP (CA_SSP + 64 * 68)         // [64]      z_prev
#define CA_TOT ((CA_SZP + 64) * 4)        // bytes = 187648

__global__ __launch_bounds__(256)
void chunk_attn()
{
    extern __shared__ float s[];
    const int blk = blockIdx.x;
    const int bh = blk >> 4, c = blk & 15;
    const int b = bh >> 4, h = bh & 15;
    const size_t row0 = (size_t)b * Ll + c * CL;
    const float* qbase = g_qkv + row0 * TD + h * Ee;
    const float* kbase = qbase + Dd;
    const float* vbase = qbase + 2 * Dd;
    const int tid = threadIdx.x;

    // load Q,K transposed; V row-major
    #pragma unroll
    for (int t = 0; t < 8; t++) {
        int id = tid + t * 256;
        int i = id >> 4, e0 = (id & 15) * 4;
        float4 q4 = *(const float4*)(qbase + (size_t)i * TD + e0);
        float4 k4 = *(const float4*)(kbase + (size_t)i * TD + e0);
        float4 v4 = *(const float4*)(vbase + (size_t)i * TD + e0);
        s[CA_SQT + (e0 + 0) * 132 + i] = q4.x;
        s[CA_SQT + (e0 + 1) * 132 + i] = q4.y;
        s[CA_SQT + (e0 + 2) * 132 + i] = q4.z;
        s[CA_SQT + (e0 + 3) * 132 + i] = q4.w;
        s[CA_SKT + (e0 + 0) * 132 + i] = k4.x;
        s[CA_SKT + (e0 + 1) * 132 + i] = k4.y;
        s[CA_SKT + (e0 + 2) * 132 + i] = k4.z;
        s[CA_SKT + (e0 + 3) * 132 + i] = k4.w;
        *(float4*)&s[CA_SV + i * 68 + e0] = v4;
    }
    // load S_prev (exclusive prefix) and z_prev
    {
        const float* kvp = g_kv + (size_t)blk * (Ee * Ee);
        #pragma unroll
        for (int t = 0; t < 4; t++) {
            int id = tid + t * 256;          // 0..1023 = 64x16 float4
            int e = id >> 4, f0 = (id & 15) * 4;
            *(float4*)&s[CA_SSP + e * 68 + f0] = *(const float4*)(kvp + e * Ee + f0);
        }
        if (tid < Ee) s[CA_SZP + tid] = g_zc[(size_t)blk * Ee + tid];
    }
    __syncthreads();

    // Phase 1: masked A = Q K^T
    {
        const int ti = tid >> 4, tj = tid & 15;
        const int i0 = ti * 8, j0 = tj * 8;
        float acc[8][8] = {};
        for (int e = 0; e < Ee; e++) {
            float q8[8], k8[8];
            *(float4*)&q8[0] = *(float4*)&s[CA_SQT + e * 132 + i0];
            *(float4*)&q8[4] = *(float4*)&s[CA_SQT + e * 132 + i0 + 4];
            *(float4*)&k8[0] = *(float4*)&s[CA_SKT + e * 132 + j0];
            *(float4*)&k8[4] = *(float4*)&s[CA_SKT + e * 132 + j0 + 4];
            #pragma unroll
            for (int r = 0; r < 8; r++)
                #pragma unroll
                for (int t = 0; t < 8; t++)
                    acc[r][t] = fmaf(q8[r], k8[t], acc[r][t]);
        }
        #pragma unroll
        for (int r = 0; r < 8; r++)
            #pragma unroll
            for (int t = 0; t < 8; t++) {
                const int i = i0 + r, j = j0 + t;
                s[CA_SA + i * 132 + j] = (j <= i) ? acc[r][t] : 0.f;
            }
    }
    __syncthreads();

    // Phase 2: num = A V + Q S_prev ; den = rowsum(A) + q.z_prev
    {
        const int ti = tid >> 3, tf = tid & 7;
        const int i0 = ti * 4, f0 = tf * 8;
        float acc[4][8] = {};
        float den[4] = {0.f, 0.f, 0.f, 0.f};

        for (int j = 0; j < CL; j++) {
            float a4[4];
            #pragma unroll
            for (int r = 0; r < 4; r++) a4[r] = s[CA_SA + (i0 + r) * 132 + j];
            float v8[8];
            *(float4*)&v8[0] = *(float4*)&s[CA_SV + j * 68 + f0];
            *(float4*)&v8[4] = *(float4*)&s[CA_SV + j * 68 + f0 + 4];
            #pragma unroll
            for (int r = 0; r < 4; r++) {
                den[r] += a4[r];
                #pragma unroll
                for (int t = 0; t < 8; t++)
                    acc[r][t] = fmaf(a4[r], v8[t], acc[r][t]);
            }
        }
        for (int e = 0; e < Ee; e++) {
            float q4[4];
            #pragma unroll
            for (int r = 0; r < 4; r++) q4[r] = s[CA_SQT + e * 132 + i0 + r];
            float s8[8];
            *(float4*)&s8[0] = *(float4*)&s[CA_SSP + e * 68 + f0];
            *(float4*)&s8[4] = *(float4*)&s[CA_SSP + e * 68 + f0 + 4];
            const float zz = s[CA_SZP + e];
            #pragma unroll
            for (int r = 0; r < 4; r++) {
                den[r] = fmaf(q4[r], zz, den[r]);
                #pragma unroll
                for (int t = 0; t < 8; t++)
                    acc[r][t] = fmaf(q4[r], s8[t], acc[r][t]);
            }
        }
        #pragma unroll
        for (int r = 0; r < 4; r++) {
            const float inv = 1.f / (den[r] + 1e-4f);
            float* op = g_attn + (row0 + i0 + r) * Dd + h * Ee + f0;
            float4 o0, o1;
            o0.x = acc[r][0] * inv; o0.y = acc[r][1] * inv;
            o0.z = acc[r][2] * inv; o0.w = acc[r][3] * inv;
            o1.x = acc[r][4] * inv; o1.y = acc[r][5] * inv;
            o1.z = acc[r][6] * inv; o1.w = acc[r][7] * inv;
            *(float4*)op = o0;
            *(float4*)(op + 4) = o1;
        }
    }
}

// ---------------------------------------------------------------------------
// In-place LayerNorm over rows of d_out (4096 rows x 1024).
// ---------------------------------------------------------------------------
__global__ __launch_bounds__(256)
void layernorm_inplace(float* __restrict__ out,
                       const float* __restrict__ gamma,
                       const float* __restrict__ beta)
{
    const int row = blockIdx.x;
    float* p = out + (size_t)row * Dd;
    const int tid = threadIdx.x;

    float4 v = ((const float4*)p)[tid];
    float s = v.x + v.y + v.z + v.w;
    float q = v.x * v.x + v.y * v.y + v.z * v.z + v.w * v.w;

    #pragma unroll
    for (int o = 16; o > 0; o >>= 1) {
        s += __shfl_xor_sync(0xffffffffu, s, o);
        q += __shfl_xor_sync(0xffffffffu, q, o);
    }
    __shared__ float ss[8], sqr[8];
    const int w = tid >> 5, lane = tid & 31;
    if (lane == 0) { ss[w] = s; sqr[w] = q; }
    __syncthreads();
    if (w == 0) {
        s = (lane < 8) ? ss[lane] : 0.f;
        q = (lane < 8) ? sqr[lane] : 0.f;
        #pragma unroll
        for (int o = 4; o > 0; o >>= 1) {
            s += __shfl_xor_sync(0xffffffffu, s, o);
            q += __shfl_xor_sync(0xffffffffu, q, o);
        }
        if (lane == 0) { ss[0] = s; sqr[0] = q; }
    }
    __syncthreads();

    const float mu  = ss[0] * (1.f / 1024.f);
    const float var = sqr[0] * (1.f / 1024.f) - mu * mu;
    const float inv = rsqrtf(var + 1e-5f);

    float4 gv = ((const float4*)gamma)[tid];
    float4 bv = ((const float4*)beta)[tid];
    float4 o4;
    o4.x = (v.x - mu) * inv * gv.x + bv.x;
    o4.y = (v.y - mu) * inv * gv.y + bv.y;
    o4.z = (v.z - mu) * inv * gv.z + bv.z;
    o4.w = (v.w - mu) * inv * gv.w + bv.w;
    ((float4*)p)[tid] = o4;
}

// ---------------------------------------------------------------------------
extern "C" void kernel_launch(void* const* d_in, const int* in_sizes, int n_in,
                              void* d_out, int out_size)
{
    const float* x     = (const float*)d_in[0];
    const float* Wqkv  = (const float*)d_in[1];
    const float* bqkv  = (const float*)d_in[2];
    const float* Wout  = (const float*)d_in[3];
    const float* bout  = (const float*)d_in[4];
    const float* gamma = (const float*)d_in[5];
    const float* beta  = (const float*)d_in[6];
    float* out = (float*)d_out;

    cudaFuncSetAttribute(mma_gemm<true>,  cudaFuncAttributeMaxDynamicSharedMemorySize, GSM);
    cudaFuncSetAttribute(mma_gemm<false>, cudaFuncAttributeMaxDynamicSharedMemorySize, GSM);
    cudaFuncSetAttribute(chunk_kv,   cudaFuncAttributeMaxDynamicSharedMemorySize, CK_TOT);
    cudaFuncSetAttribute(chunk_attn, cudaFuncAttributeMaxDynamicSharedMemorySize, CA_TOT);

    __nv_bfloat16 *xh, *xl, *wqh, *wql, *woh, *wol, *ah, *al;
    cudaGetSymbolAddress((void**)&xh,  g_xh);
    cudaGetSymbolAddress((void**)&xl,  g_xl);
    cudaGetSymbolAddress((void**)&wqh, g_wqh);
    cudaGetSymbolAddress((void**)&wql, g_wql);
    cudaGetSymbolAddress((void**)&woh, g_woh);
    cudaGetSymbolAddress((void**)&wol, g_wol);
    cudaGetSymbolAddress((void**)&ah,  g_ah);
    cudaGetSymbolAddress((void**)&al,  g_al);
    float* attn;
    cudaGetSymbolAddress((void**)&attn, g_attn);

    // 0) bf16 splits of x and weights
    split_bf16<<<(Mrows * Kdim / 4 + 255) / 256, 256>>>(x, xh, xl, Mrows * Kdim / 4);
    split_bf16<<<(TD * Kdim / 4 + 255) / 256, 256>>>(Wqkv, wqh, wql, TD * Kdim / 4);
    split_bf16<<<(Dd * Kdim / 4 + 255) / 256, 256>>>(Wout, woh, wol, Dd * Kdim / 4);

    // 1) QKV projection (mma.sync) + bias + feature maps -> g_qkv
    mma_gemm<true><<<dim3(TD / 128, Mrows / 128), 256, GSM>>>(bqkv, nullptr);

    // 2) Chunked causal linear attention -> g_attn
    chunk_kv<<<Bb * Hh * NC, 256, CK_TOT>>>();
    prefix_kv<<<Bb * Hh, 256>>>();
    chunk_attn<<<Bb * Hh * NC, 256, CA_TOT>>>();

    // 2b) split attention output for the out-proj MMA
    split_bf16<<<(Mrows * Kdim / 4 + 255) / 256, 256>>>(attn, ah, al, Mrows * Kdim / 4);

    // 3) Output projection (mma.sync) + bias -> d_out
    mma_gemm<false><<<dim3(Dd / 128, Mrows / 128), 256, GSM>>>(bout, out);

    // 4) LayerNorm in place on d_out
    layernorm_inplace<<<Mrows, 256>>>(out, gamma, beta);
}

// round 9
// speedup vs baseline: 2.9581x; 1.0343x over previous
#include <cuda_runtime.h>
#include <cuda_bf16.h>
#include <math.h>
#include <stdint.h>

// Problem constants (fixed shapes)
#define Bb 2
#define Ll 2048
#define Dd 1024
#define Hh 16
#define Ee 64
#define TD 3072          // 3*D
#define Mrows 4096       // B*L
#define Kdim 1024
#define CL 128           // chunk length
#define NC 16            // chunks per (b,h) sequence

// ---------------------------------------------------------------------------
// Device scratch (no allocation allowed)
// ---------------------------------------------------------------------------
__device__ float g_qkv[(size_t)Mrows * TD];    // feature-mapped q,k and raw v (fp32)
__device__ float g_kv[(size_t)Bb * Hh * NC * Ee * Ee];  // per-chunk KV sums -> exclusive prefixes
__device__ float g_zc[(size_t)Bb * Hh * NC * Ee];       // per-chunk k sums  -> exclusive prefixes

// bf16 hi/lo splits
__device__ __nv_bfloat16 g_xh[(size_t)Mrows * Kdim];
__device__ __nv_bfloat16 g_xl[(size_t)Mrows * Kdim];
__device__ __nv_bfloat16 g_wqh[(size_t)TD * Kdim];
__device__ __nv_bfloat16 g_wql[(size_t)TD * Kdim];
__device__ __nv_bfloat16 g_woh[(size_t)Dd * Kdim];
__device__ __nv_bfloat16 g_wol[(size_t)Dd * Kdim];
__device__ __nv_bfloat16 g_ah[(size_t)Mrows * Kdim];   // attention output hi (written by chunk_attn)
__device__ __nv_bfloat16 g_al[(size_t)Mrows * Kdim];   // attention output lo

// ---------------------------------------------------------------------------
// PTX helpers (base sm_100 feature set: mma.sync, ldmatrix, cp.async)
// ---------------------------------------------------------------------------
__device__ __forceinline__ uint32_t smem_u32(const void* p) {
    uint32_t a;
    asm("{ .reg .u64 t; cvta.to.shared.u64 t, %1; cvt.u32.u64 %0, t; }" : "=r"(a) : "l"(p));
    return a;
}

#define CP16(dst, src) \
    asm volatile("cp.async.cg.shared.global [%0], [%1], 16;" :: "r"(dst), "l"(src))
#define CP_COMMIT() asm volatile("cp.async.commit_group;" ::: "memory")
#define CP_WAIT0()  asm volatile("cp.async.wait_group 0;" ::: "memory")

#define LDSM4(r0, r1, r2, r3, addr) \
    asm volatile("ldmatrix.sync.aligned.m8n8.x4.shared.b16 {%0,%1,%2,%3}, [%4];" \
        : "=r"(r0), "=r"(r1), "=r"(r2), "=r"(r3) : "r"(addr))

#define MMA(d, a, b) \
    asm volatile("mma.sync.aligned.m16n8k16.row.col.f32.bf16.bf16.f32 " \
        "{%0,%1,%2,%3},{%4,%5,%6,%7},{%8,%9},{%0,%1,%2,%3};" \
        : "+f"((d)[0]), "+f"((d)[1]), "+f"((d)[2]), "+f"((d)[3]) \
        : "r"((a)[0]), "r"((a)[1]), "r"((a)[2]), "r"((a)[3]), \
          "r"((b)[0]), "r"((b)[1]))

// ---------------------------------------------------------------------------
// bf16 split: hi = bf16(x), lo = bf16(x - hi)
// ---------------------------------------------------------------------------
__global__ __launch_bounds__(256)
void split_bf16(const float* __restrict__ s, __nv_bfloat16* __restrict__ h,
                __nv_bfloat16* __restrict__ l, int n4) {
    int i = blockIdx.x * 256 + threadIdx.x;
    if (i >= n4) return;
    float4 v = ((const float4*)s)[i];
    __nv_bfloat16 h0 = __float2bfloat16_rn(v.x);
    __nv_bfloat16 h1 = __float2bfloat16_rn(v.y);
    __nv_bfloat16 h2 = __float2bfloat16_rn(v.z);
    __nv_bfloat16 h3 = __float2bfloat16_rn(v.w);
    __nv_bfloat16 l0 = __float2bfloat16_rn(v.x - __bfloat162float(h0));
    __nv_bfloat16 l1 = __float2bfloat16_rn(v.y - __bfloat162float(h1));
    __nv_bfloat16 l2 = __float2bfloat16_rn(v.z - __bfloat162float(h2));
    __nv_bfloat16 l3 = __float2bfloat16_rn(v.w - __bfloat162float(h3));
    ((__nv_bfloat162*)h)[2 * i]     = __nv_bfloat162(h0, h1);
    ((__nv_bfloat162*)h)[2 * i + 1] = __nv_bfloat162(h2, h3);
    ((__nv_bfloat162*)l)[2 * i]     = __nv_bfloat162(l0, l1);
    ((__nv_bfloat162*)l)[2 * i + 1] = __nv_bfloat162(l2, l3);
}

// ---------------------------------------------------------------------------
// mma.sync GEMM: single-barrier double-buffered pipeline.
//   loop: wait(all cp.async) -> barrier -> prefetch next chunk -> compute.
// The barrier both publishes chunk kc and proves kc-1 compute finished, so
// overwriting kc-1's buffer (the prefetch target) is safe.
// ---------------------------------------------------------------------------
#define TPITCH 80
#define TSZ   (128 * TPITCH)
#define GSM   (2 * 4 * TSZ)

template<bool QKV>
__global__ __launch_bounds__(256)
void mma_gemm(const float* __restrict__ bias, float* __restrict__ Cp)
{
    constexpr int NTOT = QKV ? TD : Dd;
    extern __shared__ char sm[];
    const uint32_t sb = smem_u32(sm);

    const __nv_bfloat16* Ahp = QKV ? g_xh : g_ah;
    const __nv_bfloat16* Alp = QKV ? g_xl : g_al;
    const __nv_bfloat16* Bhp = QKV ? g_wqh : g_woh;
    const __nv_bfloat16* Blp = QKV ? g_wql : g_wol;
    float* C = QKV ? g_qkv : Cp;

    const int tid  = threadIdx.x;
    const int lane = tid & 31;
    const int wid  = tid >> 5;
    const int wm   = wid & 1;
    const int wn   = wid >> 1;
    const int m0   = blockIdx.y * 128;
    const int n0   = blockIdx.x * 128;

    const int lrow = tid >> 2;
    const int lcb  = (tid & 3) * 16;
    const int lce  = (tid & 3) * 8;

    const __nv_bfloat16* gsrc[4] = {
        Ahp + (size_t)m0 * Kdim, Alp + (size_t)m0 * Kdim,
        Bhp + (size_t)n0 * Kdim, Blp + (size_t)n0 * Kdim };

    float acc[4][4][4];
    #pragma unroll
    for (int i = 0; i < 4; i++)
        #pragma unroll
        for (int j = 0; j < 4; j++)
            #pragma unroll
            for (int r = 0; r < 4; r++) acc[i][j][r] = 0.f;

    #define ISSUE(buf, kc) do {                                               \
        const int k0_ = (kc) * 32;                                            \
        const uint32_t db_ = sb + (buf) * 4 * TSZ;                            \
        _Pragma("unroll")                                                     \
        for (int t_ = 0; t_ < 4; t_++) {                                      \
            const __nv_bfloat16* bp_ = gsrc[t_];                              \
            uint32_t ds_ = db_ + t_ * TSZ;                                    \
            CP16(ds_ + lrow * TPITCH + lcb,                                   \
                 bp_ + (size_t)lrow * Kdim + k0_ + lce);                      \
            CP16(ds_ + (lrow + 64) * TPITCH + lcb,                            \
                 bp_ + (size_t)(lrow + 64) * Kdim + k0_ + lce);               \
        }                                                                     \
    } while (0)

    ISSUE(0, 0); CP_COMMIT();

    const int r16 = lane & 15;
    const int kb8 = (lane >> 4) * 16;

    int buf = 0;
    for (int kc = 0; kc < Kdim / 32; kc++) {
        CP_WAIT0();                // chunk kc landed (only group in flight)
        __syncthreads();           // publish kc; all warps done with kc-1
        if (kc + 1 < Kdim / 32) { ISSUE(buf ^ 1, kc + 1); CP_COMMIT(); }

        const uint32_t base = sb + buf * 4 * TSZ;
        const uint32_t sAh = base, sAl = base + TSZ;
        const uint32_t sBh = base + 2 * TSZ, sBl = base + 3 * TSZ;

        #pragma unroll
        for (int ks = 0; ks < 2; ks++) {
            const int kbyte = ks * 32 + kb8;
            uint32_t ah[4][4], al[4][4], bh[4][2], bl[4][2];
            #pragma unroll
            for (int tm = 0; tm < 4; tm++) {
                const uint32_t roff = (uint32_t)(wm * 64 + tm * 16 + r16) * TPITCH + kbyte;
                LDSM4(ah[tm][0], ah[tm][1], ah[tm][2], ah[tm][3], sAh + roff);
                LDSM4(al[tm][0], al[tm][1], al[tm][2], al[tm][3], sAl + roff);
            }
            #pragma unroll
            for (int tp = 0; tp < 2; tp++) {
                const uint32_t roff = (uint32_t)(wn * 32 + tp * 16 + r16) * TPITCH + kbyte;
                uint32_t r0, r1, r2, r3;
                LDSM4(r0, r1, r2, r3, sBh + roff);
                bh[tp * 2][0] = r0; bh[tp * 2 + 1][0] = r1;
                bh[tp * 2][1] = r2; bh[tp * 2 + 1][1] = r3;
                LDSM4(r0, r1, r2, r3, sBl + roff);
                bl[tp * 2][0] = r0; bl[tp * 2 + 1][0] = r1;
                bl[tp * 2][1] = r2; bl[tp * 2 + 1][1] = r3;
            }
            #pragma unroll
            for (int tm = 0; tm < 4; tm++)
                #pragma unroll
                for (int tn = 0; tn < 4; tn++) {
                    MMA(acc[tm][tn], ah[tm], bh[tn]);
                    MMA(acc[tm][tn], ah[tm], bl[tn]);
                    MMA(acc[tm][tn], al[tm], bh[tn]);
                }
        }
        buf ^= 1;
    }
    #undef ISSUE

    #pragma unroll
    for (int tm = 0; tm < 4; tm++) {
        const int row = m0 + wm * 64 + tm * 16 + (lane >> 2);
        #pragma unroll
        for (int tn = 0; tn < 4; tn++) {
            const int col = n0 + wn * 32 + tn * 8 + (lane & 3) * 2;
            #pragma unroll
            for (int half = 0; half < 2; half++) {
                const int m = row + half * 8;
                float v0 = acc[tm][tn][half * 2 + 0] + bias[col];
                float v1 = acc[tm][tn][half * 2 + 1] + bias[col + 1];
                if (QKV) {
                    if (col < 2 * Dd) {
                        float e0 = v0 > 0.f ? v0 : (expf(v0) - 1.f);
                        float e1 = v1 > 0.f ? v1 : (expf(v1) - 1.f);
                        v0 = e0 + 1.0001f; v1 = e1 + 1.0001f;
                        if (col < Dd) { v0 *= 0.125f; v1 *= 0.125f; }
                    }
                }
                float2 o; o.x = v0; o.y = v1;
                *(float2*)(C + (size_t)m * NTOT + col) = o;
            }
        }
    }
}

// ---------------------------------------------------------------------------
// Chunked linear attention, stage A: per-chunk KV outer-product sums + k sums.
// Grid: Bb*Hh*NC = 512 blocks, 256 threads, 68 KB DYNAMIC smem.
// ---------------------------------------------------------------------------
#define CK_SK 0
#define CK_SV (CL * 68)
#define CK_TOT ((CL * 68 * 2) * 4)     // 69632 bytes

__global__ __launch_bounds__(256)
void chunk_kv()
{
    extern __shared__ float s[];
    float (*sk)[68] = (float(*)[68])(s + CK_SK);
    float (*sv)[68] = (float(*)[68])(s + CK_SV);

    const int blk = blockIdx.x;
    const int bh = blk >> 4, c = blk & 15;
    const int b = bh >> 4, h = bh & 15;
    const float* kbase = g_qkv + ((size_t)(b * Ll + c * CL)) * TD + Dd + h * Ee;
    const float* vbase = kbase + Dd;
    const int tid = threadIdx.x;

    #pragma unroll
    for (int t = 0; t < 8; t++) {
        int id = tid + t * 256;            // 0..2047 = 128 rows x 16 float4
        int i = id >> 4, c4 = (id & 15) * 4;
        *(float4*)&sk[i][c4] = *(const float4*)(kbase + (size_t)i * TD + c4);
        *(float4*)&sv[i][c4] = *(const float4*)(vbase + (size_t)i * TD + c4);
    }
    __syncthreads();

    const int te = tid >> 4, tf = tid & 15;
    const int e0 = te * 4, f0 = tf * 4;
    float acc[4][4] = {};
    float z4[4] = {0.f, 0.f, 0.f, 0.f};

    for (int i = 0; i < CL; i++) {
        float4 k4 = *(float4*)&sk[i][e0];
        float4 v4 = *(float4*)&sv[i][f0];
        float kk[4] = {k4.x, k4.y, k4.z, k4.w};
        float vv[4] = {v4.x, v4.y, v4.z, v4.w};
        #pragma unroll
        for (int r = 0; r < 4; r++) {
            #pragma unroll
            for (int q = 0; q < 4; q++) acc[r][q] = fmaf(kk[r], vv[q], acc[r][q]);
        }
        if (tf == 0) {
            #pragma unroll
            for (int r = 0; r < 4; r++) z4[r] += kk[r];
        }
    }

    float* kvo = g_kv + (size_t)blk * Ee * Ee;
    #pragma unroll
    for (int r = 0; r < 4; r++) {
        float4 o; o.x = acc[r][0]; o.y = acc[r][1]; o.z = acc[r][2]; o.w = acc[r][3];
        *(float4*)&kvo[(e0 + r) * Ee + f0] = o;
    }
    if (tf == 0) {
        float* zo = g_zc + (size_t)blk * Ee;
        #pragma unroll
        for (int r = 0; r < 4; r++) zo[e0 + r] = z4[r];
    }
}

// ---------------------------------------------------------------------------
// Stage B: in-place exclusive prefix over the NC chunks of each (b,h).
// ---------------------------------------------------------------------------
__global__ __launch_bounds__(256)
void prefix_kv()
{
    const int bh = blockIdx.x;
    const int tid = threadIdx.x;
    float* kvb = g_kv + (size_t)bh * NC * Ee * Ee;

    #pragma unroll
    for (int t = 0; t < 16; t++) {
        const int idx = tid + t * 256;
        float run = 0.f;
        #pragma unroll
        for (int c = 0; c < NC; c++) {
            float tmp = kvb[(size_t)c * (Ee * Ee) + idx];
            kvb[(size_t)c * (Ee * Ee) + idx] = run;
            run += tmp;
        }
    }
    if (tid < Ee) {
        float* zb = g_zc + (size_t)bh * NC * Ee;
        float run = 0.f;
        #pragma unroll
        for (int c = 0; c < NC; c++) {
            float tmp = zb[c * Ee + tid];
            zb[c * Ee + tid] = run;
            run += tmp;
        }
    }
}

// ---------------------------------------------------------------------------
// Stage C: per-chunk attention. Epilogue writes bf16 hi/lo splits directly
// to g_ah / g_al (feeds the out-proj MMA) — no fp32 intermediate pass.
// ---------------------------------------------------------------------------
#define CA_SQT 0                          // [64][132] Q transposed
#define CA_SKT (64 * 132)                 // [64][132] K transposed
#define CA_SV  (CA_SKT + 64 * 132)        // [128][68] V
#define CA_SA  (CA_SV + 128 * 68)         // [128][132] masked A
#define CA_SSP (CA_SA + 128 * 132)        // [64][68]  S_prev
#define CA_SZP (CA_SSP + 64 * 68)         // [64]      z_prev
#define CA_TOT ((CA_SZP + 64) * 4)        // bytes = 187648

__global__ __launch_bounds__(256)
void chunk_attn()
{
    extern __shared__ float s[];
    const int blk = blockIdx.x;
    const int bh = blk >> 4, c = blk & 15;
    const int b = bh >> 4, h = bh & 15;
    const size_t row0 = (size_t)b * Ll + c * CL;
    const float* qbase = g_qkv + row0 * TD + h * Ee;
    const float* kbase = qbase + Dd;
    const float* vbase = qbase + 2 * Dd;
    const int tid = threadIdx.x;

    // load Q,K transposed; V row-major
    #pragma unroll
    for (int t = 0; t < 8; t++) {
        int id = tid + t * 256;
        int i = id >> 4, e0 = (id & 15) * 4;
        float4 q4 = *(const float4*)(qbase + (size_t)i * TD + e0);
        float4 k4 = *(const float4*)(kbase + (size_t)i * TD + e0);
        float4 v4 = *(const float4*)(vbase + (size_t)i * TD + e0);
        s[CA_SQT + (e0 + 0) * 132 + i] = q4.x;
        s[CA_SQT + (e0 + 1) * 132 + i] = q4.y;
        s[CA_SQT + (e0 + 2) * 132 + i] = q4.z;
        s[CA_SQT + (e0 + 3) * 132 + i] = q4.w;
        s[CA_SKT + (e0 + 0) * 132 + i] = k4.x;
        s[CA_SKT + (e0 + 1) * 132 + i] = k4.y;
        s[CA_SKT + (e0 + 2) * 132 + i] = k4.z;
        s[CA_SKT + (e0 + 3) * 132 + i] = k4.w;
        *(float4*)&s[CA_SV + i * 68 + e0] = v4;
    }
    // load S_prev (exclusive prefix) and z_prev
    {
        const float* kvp = g_kv + (size_t)blk * (Ee * Ee);
        #pragma unroll
        for (int t = 0; t < 4; t++) {
            int id = tid + t * 256;          // 0..1023 = 64x16 float4
            int e = id >> 4, f0 = (id & 15) * 4;
            *(float4*)&s[CA_SSP + e * 68 + f0] = *(const float4*)(kvp + e * Ee + f0);
        }
        if (tid < Ee) s[CA_SZP + tid] = g_zc[(size_t)blk * Ee + tid];
    }
    __syncthreads();

    // Phase 1: masked A = Q K^T
    {
        const int ti = tid >> 4, tj = tid & 15;
        const int i0 = ti * 8, j0 = tj * 8;
        float acc[8][8] = {};
        for (int e = 0; e < Ee; e++) {
            float q8[8], k8[8];
            *(float4*)&q8[0] = *(float4*)&s[CA_SQT + e * 132 + i0];
            *(float4*)&q8[4] = *(float4*)&s[CA_SQT + e * 132 + i0 + 4];
            *(float4*)&k8[0] = *(float4*)&s[CA_SKT + e * 132 + j0];
            *(float4*)&k8[4] = *(float4*)&s[CA_SKT + e * 132 + j0 + 4];
            #pragma unroll
            for (int r = 0; r < 8; r++)
                #pragma unroll
                for (int t = 0; t < 8; t++)
                    acc[r][t] = fmaf(q8[r], k8[t], acc[r][t]);
        }
        #pragma unroll
        for (int r = 0; r < 8; r++)
            #pragma unroll
            for (int t = 0; t < 8; t++) {
                const int i = i0 + r, j = j0 + t;
                s[CA_SA + i * 132 + j] = (j <= i) ? acc[r][t] : 0.f;
            }
    }
    __syncthreads();

    // Phase 2: num = A V + Q S_prev ; den = rowsum(A) + q.z_prev
    {
        const int ti = tid >> 3, tf = tid & 7;
        const int i0 = ti * 4, f0 = tf * 8;
        float acc[4][8] = {};
        float den[4] = {0.f, 0.f, 0.f, 0.f};

        for (int j = 0; j < CL; j++) {
            float a4[4];
            #pragma unroll
            for (int r = 0; r < 4; r++) a4[r] = s[CA_SA + (i0 + r) * 132 + j];
            float v8[8];
            *(float4*)&v8[0] = *(float4*)&s[CA_SV + j * 68 + f0];
            *(float4*)&v8[4] = *(float4*)&s[CA_SV + j * 68 + f0 + 4];
            #pragma unroll
            for (int r = 0; r < 4; r++) {
                den[r] += a4[r];
                #pragma unroll
                for (int t = 0; t < 8; t++)
                    acc[r][t] = fmaf(a4[r], v8[t], acc[r][t]);
            }
        }
        for (int e = 0; e < Ee; e++) {
            float q4[4];
            #pragma unroll
            for (int r = 0; r < 4; r++) q4[r] = s[CA_SQT + e * 132 + i0 + r];
            float s8[8];
            *(float4*)&s8[0] = *(float4*)&s[CA_SSP + e * 68 + f0];
            *(float4*)&s8[4] = *(float4*)&s[CA_SSP + e * 68 + f0 + 4];
            const float zz = s[CA_SZP + e];
            #pragma unroll
            for (int r = 0; r < 4; r++) {
                den[r] = fmaf(q4[r], zz, den[r]);
                #pragma unroll
                for (int t = 0; t < 8; t++)
                    acc[r][t] = fmaf(q4[r], s8[t], acc[r][t]);
            }
        }
        #pragma unroll
        for (int r = 0; r < 4; r++) {
            const float inv = 1.f / (den[r] + 1e-4f);
            const size_t obase = (row0 + i0 + r) * Kdim + h * Ee + f0;
            __nv_bfloat16 hv[8], lv[8];
            #pragma unroll
            for (int t = 0; t < 8; t++) {
                const float v = acc[r][t] * inv;
                hv[t] = __float2bfloat16_rn(v);
                lv[t] = __float2bfloat16_rn(v - __bfloat162float(hv[t]));
            }
            *(uint4*)(g_ah + obase) = *(uint4*)hv;
            *(uint4*)(g_al + obase) = *(uint4*)lv;
        }
    }
}

// ---------------------------------------------------------------------------
// In-place LayerNorm over rows of d_out (4096 rows x 1024).
// ---------------------------------------------------------------------------
__global__ __launch_bounds__(256)
void layernorm_inplace(float* __restrict__ out,
                       const float* __restrict__ gamma,
                       const float* __restrict__ beta)
{
    const int row = blockIdx.x;
    float* p = out + (size_t)row * Dd;
    const int tid = threadIdx.x;

    float4 v = ((const float4*)p)[tid];
    float s = v.x + v.y + v.z + v.w;
    float q = v.x * v.x + v.y * v.y + v.z * v.z + v.w * v.w;

    #pragma unroll
    for (int o = 16; o > 0; o >>= 1) {
        s += __shfl_xor_sync(0xffffffffu, s, o);
        q += __shfl_xor_sync(0xffffffffu, q, o);
    }
    __shared__ float ss[8], sqr[8];
    const int w = tid >> 5, lane = tid & 31;
    if (lane == 0) { ss[w] = s; sqr[w] = q; }
    __syncthreads();
    if (w == 0) {
        s = (lane < 8) ? ss[lane] : 0.f;
        q = (lane < 8) ? sqr[lane] : 0.f;
        #pragma unroll
        for (int o = 4; o > 0; o >>= 1) {
            s += __shfl_xor_sync(0xffffffffu, s, o);
            q += __shfl_xor_sync(0xffffffffu, q, o);
        }
        if (lane == 0) { ss[0] = s; sqr[0] = q; }
    }
    __syncthreads();

    const float mu  = ss[0] * (1.f / 1024.f);
    const float var = sqr[0] * (1.f / 1024.f) - mu * mu;
    const float inv = rsqrtf(var + 1e-5f);

    float4 gv = ((const float4*)gamma)[tid];
    float4 bv = ((const float4*)beta)[tid];
    float4 o4;
    o4.x = (v.x - mu) * inv * gv.x + bv.x;
    o4.y = (v.y - mu) * inv * gv.y + bv.y;
    o4.z = (v.z - mu) * inv * gv.z + bv.z;
    o4.w = (v.w - mu) * inv * gv.w + bv.w;
    ((float4*)p)[tid] = o4;
}

// ---------------------------------------------------------------------------
extern "C" void kernel_launch(void* const* d_in, const int* in_sizes, int n_in,
                              void* d_out, int out_size)
{
    const float* x     = (const float*)d_in[0];
    const float* Wqkv  = (const float*)d_in[1];
    const float* bqkv  = (const float*)d_in[2];
    const float* Wout  = (const float*)d_in[3];
    const float* bout  = (const float*)d_in[4];
    const float* gamma = (const float*)d_in[5];
    const float* beta  = (const float*)d_in[6];
    float* out = (float*)d_out;

    cudaFuncSetAttribute(mma_gemm<true>,  cudaFuncAttributeMaxDynamicSharedMemorySize, GSM);
    cudaFuncSetAttribute(mma_gemm<false>, cudaFuncAttributeMaxDynamicSharedMemorySize, GSM);
    cudaFuncSetAttribute(chunk_kv,   cudaFuncAttributeMaxDynamicSharedMemorySize, CK_TOT);
    cudaFuncSetAttribute(chunk_attn, cudaFuncAttributeMaxDynamicSharedMemorySize, CA_TOT);

    __nv_bfloat16 *xh, *xl, *wqh, *wql, *woh, *wol;
    cudaGetSymbolAddress((void**)&xh,  g_xh);
    cudaGetSymbolAddress((void**)&xl,  g_xl);
    cudaGetSymbolAddress((void**)&wqh, g_wqh);
    cudaGetSymbolAddress((void**)&wql, g_wql);
    cudaGetSymbolAddress((void**)&woh, g_woh);
    cudaGetSymbolAddress((void**)&wol, g_wol);

    // 0) bf16 splits of x and weights
    split_bf16<<<(Mrows * Kdim / 4 + 255) / 256, 256>>>(x, xh, xl, Mrows * Kdim / 4);
    split_bf16<<<(TD * Kdim / 4 + 255) / 256, 256>>>(Wqkv, wqh, wql, TD * Kdim / 4);
    split_bf16<<<(Dd * Kdim / 4 + 255) / 256, 256>>>(Wout, woh, wol, Dd * Kdim / 4);

    // 1) QKV projection (mma.sync) + bias + feature maps -> g_qkv
    mma_gemm<true><<<dim3(TD / 128, Mrows / 128), 256, GSM>>>(bqkv, nullptr);

    // 2) Chunked causal linear attention -> g_ah/g_al (bf16 split, fused)
    chunk_kv<<<Bb * Hh * NC, 256, CK_TOT>>>();
    prefix_kv<<<Bb * Hh, 256>>>();
    chunk_attn<<<Bb * Hh * NC, 256, CA_TOT>>>();

    // 3) Output projection (mma.sync) + bias -> d_out
    mma_gemm<false><<<dim3(Dd / 128, Mrows / 128), 256, GSM>>>(bout, out);

    // 4) LayerNorm in place on d_out
    layernorm_inplace<<<Mrows, 256>>>(out, gamma, beta);
}

// round 12
// speedup vs baseline: 2.9593x; 1.0004x over previous
#include <cuda_runtime.h>
#include <cuda_bf16.h>
#include <math.h>
#include <stdint.h>

// Problem constants (fixed shapes)
#define Bb 2
#define Ll 2048
#define Dd 1024
#define Hh 16
#define Ee 64
#define TD 3072          // 3*D
#define Mrows 4096       // B*L
#define Kdim 1024
#define CL 128           // chunk length
#define NC 16            // chunks per (b,h) sequence

// ---------------------------------------------------------------------------
// Device scratch (no allocation allowed)
// ---------------------------------------------------------------------------
__device__ float g_qkv[(size_t)Mrows * TD];    // feature-mapped q,k and raw v (fp32)
__device__ float g_kv[(size_t)Bb * Hh * NC * Ee * Ee];  // per-chunk KV sums -> exclusive prefixes
__device__ float g_zc[(size_t)Bb * Hh * NC * Ee];       // per-chunk k sums  -> exclusive prefixes

// bf16 hi/lo splits
__device__ __nv_bfloat16 g_xh[(size_t)Mrows * Kdim];
__device__ __nv_bfloat16 g_xl[(size_t)Mrows * Kdim];
__device__ __nv_bfloat16 g_wqh[(size_t)TD * Kdim];
__device__ __nv_bfloat16 g_wql[(size_t)TD * Kdim];
__device__ __nv_bfloat16 g_woh[(size_t)Dd * Kdim];
__device__ __nv_bfloat16 g_wol[(size_t)Dd * Kdim];
__device__ __nv_bfloat16 g_ah[(size_t)Mrows * Kdim];   // attention output hi (written by chunk_attn)
__device__ __nv_bfloat16 g_al[(size_t)Mrows * Kdim];   // attention output lo

// ---------------------------------------------------------------------------
// PTX helpers (base sm_100 feature set: mma.sync, ldmatrix, cp.async)
// ---------------------------------------------------------------------------
__device__ __forceinline__ uint32_t smem_u32(const void* p) {
    uint32_t a;
    asm("{ .reg .u64 t; cvta.to.shared.u64 t, %1; cvt.u32.u64 %0, t; }" : "=r"(a) : "l"(p));
    return a;
}

#define CP16(dst, src) \
    asm volatile("cp.async.cg.shared.global [%0], [%1], 16;" :: "r"(dst), "l"(src))
#define CP_COMMIT() asm volatile("cp.async.commit_group;" ::: "memory")
#define CP_WAIT0()  asm volatile("cp.async.wait_group 0;" ::: "memory")

#define LDSM4(r0, r1, r2, r3, addr) \
    asm volatile("ldmatrix.sync.aligned.m8n8.x4.shared.b16 {%0,%1,%2,%3}, [%4];" \
        : "=r"(r0), "=r"(r1), "=r"(r2), "=r"(r3) : "r"(addr))

#define MMA(d, a, b) \
    asm volatile("mma.sync.aligned.m16n8k16.row.col.f32.bf16.bf16.f32 " \
        "{%0,%1,%2,%3},{%4,%5,%6,%7},{%8,%9},{%0,%1,%2,%3};" \
        : "+f"((d)[0]), "+f"((d)[1]), "+f"((d)[2]), "+f"((d)[3]) \
        : "r"((a)[0]), "r"((a)[1]), "r"((a)[2]), "r"((a)[3]), \
          "r"((b)[0]), "r"((b)[1]))

// ---------------------------------------------------------------------------
// bf16 split: hi = bf16(x), lo = bf16(x - hi)
// ---------------------------------------------------------------------------
__global__ __launch_bounds__(256)
void split_bf16(const float* __restrict__ s, __nv_bfloat16* __restrict__ h,
                __nv_bfloat16* __restrict__ l, int n4) {
    int i = blockIdx.x * 256 + threadIdx.x;
    if (i >= n4) return;
    float4 v = ((const float4*)s)[i];
    __nv_bfloat16 h0 = __float2bfloat16_rn(v.x);
    __nv_bfloat16 h1 = __float2bfloat16_rn(v.y);
    __nv_bfloat16 h2 = __float2bfloat16_rn(v.z);
    __nv_bfloat16 h3 = __float2bfloat16_rn(v.w);
    __nv_bfloat16 l0 = __float2bfloat16_rn(v.x - __bfloat162float(h0));
    __nv_bfloat16 l1 = __float2bfloat16_rn(v.y - __bfloat162float(h1));
    __nv_bfloat16 l2 = __float2bfloat16_rn(v.z - __bfloat162float(h2));
    __nv_bfloat16 l3 = __float2bfloat16_rn(v.w - __bfloat162float(h3));
    ((__nv_bfloat162*)h)[2 * i]     = __nv_bfloat162(h0, h1);
    ((__nv_bfloat162*)h)[2 * i + 1] = __nv_bfloat162(h2, h3);
    ((__nv_bfloat162*)l)[2 * i]     = __nv_bfloat162(l0, l1);
    ((__nv_bfloat162*)l)[2 * i + 1] = __nv_bfloat162(l2, l3);
}

// ---------------------------------------------------------------------------
// mma.sync GEMM: single-barrier double-buffered pipeline.
// MMA term loop hoisted outside tile loops: same-accumulator reuse distance
// is 16 independent MMAs (covers HMMA latency within one warp).
// ---------------------------------------------------------------------------
#define TPITCH 80
#define TSZ   (128 * TPITCH)
#define GSM   (2 * 4 * TSZ)

template<bool QKV>
__global__ __launch_bounds__(256)
void mma_gemm(const float* __restrict__ bias, float* __restrict__ Cp)
{
    constexpr int NTOT = QKV ? TD : Dd;
    extern __shared__ char sm[];
    const uint32_t sb = smem_u32(sm);

    const __nv_bfloat16* Ahp = QKV ? g_xh : g_ah;
    const __nv_bfloat16* Alp = QKV ? g_xl : g_al;
    const __nv_bfloat16* Bhp = QKV ? g_wqh : g_woh;
    const __nv_bfloat16* Blp = QKV ? g_wql : g_wol;
    float* C = QKV ? g_qkv : Cp;

    const int tid  = threadIdx.x;
    const int lane = tid & 31;
    const int wid  = tid >> 5;
    const int wm   = wid & 1;
    const int wn   = wid >> 1;
    const int m0   = blockIdx.y * 128;
    const int n0   = blockIdx.x * 128;

    const int lrow = tid >> 2;
    const int lcb  = (tid & 3) * 16;
    const int lce  = (tid & 3) * 8;

    const __nv_bfloat16* gsrc[4] = {
        Ahp + (size_t)m0 * Kdim, Alp + (size_t)m0 * Kdim,
        Bhp + (size_t)n0 * Kdim, Blp + (size_t)n0 * Kdim };

    float acc[4][4][4];
    #pragma unroll
    for (int i = 0; i < 4; i++)
        #pragma unroll
        for (int j = 0; j < 4; j++)
            #pragma unroll
            for (int r = 0; r < 4; r++) acc[i][j][r] = 0.f;

    #define ISSUE(buf, kc) do {                                               \
        const int k0_ = (kc) * 32;                                            \
        const uint32_t db_ = sb + (buf) * 4 * TSZ;                            \
        _Pragma("unroll")                                                     \
        for (int t_ = 0; t_ < 4; t_++) {                                      \
            const __nv_bfloat16* bp_ = gsrc[t_];                              \
            uint32_t ds_ = db_ + t_ * TSZ;                                    \
            CP16(ds_ + lrow * TPITCH + lcb,                                   \
                 bp_ + (size_t)lrow * Kdim + k0_ + lce);                      \
            CP16(ds_ + (lrow + 64) * TPITCH + lcb,                            \
                 bp_ + (size_t)(lrow + 64) * Kdim + k0_ + lce);               \
        }                                                                     \
    } while (0)

    ISSUE(0, 0); CP_COMMIT();

    const int r16 = lane & 15;
    const int kb8 = (lane >> 4) * 16;

    int buf = 0;
    for (int kc = 0; kc < Kdim / 32; kc++) {
        CP_WAIT0();                // chunk kc landed (only group in flight)
        __syncthreads();           // publish kc; all warps done with kc-1
        if (kc + 1 < Kdim / 32) { ISSUE(buf ^ 1, kc + 1); CP_COMMIT(); }

        const uint32_t base = sb + buf * 4 * TSZ;
        const uint32_t sAh = base, sAl = base + TSZ;
        const uint32_t sBh = base + 2 * TSZ, sBl = base + 3 * TSZ;

        #pragma unroll
        for (int ks = 0; ks < 2; ks++) {
            const int kbyte = ks * 32 + kb8;
            uint32_t ah[4][4], al[4][4], bh[4][2], bl[4][2];
            #pragma unroll
            for (int tm = 0; tm < 4; tm++) {
                const uint32_t roff = (uint32_t)(wm * 64 + tm * 16 + r16) * TPITCH + kbyte;
                LDSM4(ah[tm][0], ah[tm][1], ah[tm][2], ah[tm][3], sAh + roff);
                LDSM4(al[tm][0], al[tm][1], al[tm][2], al[tm][3], sAl + roff);
            }
            #pragma unroll
            for (int tp = 0; tp < 2; tp++) {
                const uint32_t roff = (uint32_t)(wn * 32 + tp * 16 + r16) * TPITCH + kbyte;
                uint32_t r0, r1, r2, r3;
                LDSM4(r0, r1, r2, r3, sBh + roff);
                bh[tp * 2][0] = r0; bh[tp * 2 + 1][0] = r1;
                bh[tp * 2][1] = r2; bh[tp * 2 + 1][1] = r3;
                LDSM4(r0, r1, r2, r3, sBl + roff);
                bl[tp * 2][0] = r0; bl[tp * 2 + 1][0] = r1;
                bl[tp * 2][1] = r2; bl[tp * 2 + 1][1] = r3;
            }
            // term-major order: 16 independent MMAs between same-acc reuses
            #pragma unroll
            for (int tm = 0; tm < 4; tm++)
                #pragma unroll
                for (int tn = 0; tn < 4; tn++)
                    MMA(acc[tm][tn], ah[tm], bh[tn]);
            #pragma unroll
            for (int tm = 0; tm < 4; tm++)
                #pragma unroll
                for (int tn = 0; tn < 4; tn++)
                    MMA(acc[tm][tn], ah[tm], bl[tn]);
            #pragma unroll
            for (int tm = 0; tm < 4; tm++)
                #pragma unroll
                for (int tn = 0; tn < 4; tn++)
                    MMA(acc[tm][tn], al[tm], bh[tn]);
        }
        buf ^= 1;
    }
    #undef ISSUE

    #pragma unroll
    for (int tm = 0; tm < 4; tm++) {
        const int row = m0 + wm * 64 + tm * 16 + (lane >> 2);
        #pragma unroll
        for (int tn = 0; tn < 4; tn++) {
            const int col = n0 + wn * 32 + tn * 8 + (lane & 3) * 2;
            #pragma unroll
            for (int half = 0; half < 2; half++) {
                const int m = row + half * 8;
                float v0 = acc[tm][tn][half * 2 + 0] + bias[col];
                float v1 = acc[tm][tn][half * 2 + 1] + bias[col + 1];
                if (QKV) {
                    if (col < 2 * Dd) {
                        float e0 = v0 > 0.f ? v0 : (expf(v0) - 1.f);
                        float e1 = v1 > 0.f ? v1 : (expf(v1) - 1.f);
                        v0 = e0 + 1.0001f; v1 = e1 + 1.0001f;
                        if (col < Dd) { v0 *= 0.125f; v1 *= 0.125f; }
                    }
                }
                float2 o; o.x = v0; o.y = v1;
                *(float2*)(C + (size_t)m * NTOT + col) = o;
            }
        }
    }
}

// ---------------------------------------------------------------------------
// Chunked linear attention, stage A: per-chunk KV outer-product sums + k sums.
// ---------------------------------------------------------------------------
#define CK_SK 0
#define CK_SV (CL * 68)
#define CK_TOT ((CL * 68 * 2) * 4)     // 69632 bytes

__global__ __launch_bounds__(256)
void chunk_kv()
{
    extern __shared__ float s[];
    float (*sk)[68] = (float(*)[68])(s + CK_SK);
    float (*sv)[68] = (float(*)[68])(s + CK_SV);

    const int blk = blockIdx.x;
    const int bh = blk >> 4, c = blk & 15;
    const int b = bh >> 4, h = bh & 15;
    const float* kbase = g_qkv + ((size_t)(b * Ll + c * CL)) * TD + Dd + h * Ee;
    const float* vbase = kbase + Dd;
    const int tid = threadIdx.x;

    #pragma unroll
    for (int t = 0; t < 8; t++) {
        int id = tid + t * 256;            // 0..2047 = 128 rows x 16 float4
        int i = id >> 4, c4 = (id & 15) * 4;
        *(float4*)&sk[i][c4] = *(const float4*)(kbase + (size_t)i * TD + c4);
        *(float4*)&sv[i][c4] = *(const float4*)(vbase + (size_t)i * TD + c4);
    }
    __syncthreads();

    const int te = tid >> 4, tf = tid & 15;
    const int e0 = te * 4, f0 = tf * 4;
    float acc[4][4] = {};
    float z4[4] = {0.f, 0.f, 0.f, 0.f};

    for (int i = 0; i < CL; i++) {
        float4 k4 = *(float4*)&sk[i][e0];
        float4 v4 = *(float4*)&sv[i][f0];
        float kk[4] = {k4.x, k4.y, k4.z, k4.w};
        float vv[4] = {v4.x, v4.y, v4.z, v4.w};
        #pragma unroll
        for (int r = 0; r < 4; r++) {
            #pragma unroll
            for (int q = 0; q < 4; q++) acc[r][q] = fmaf(kk[r], vv[q], acc[r][q]);
        }
        if (tf == 0) {
            #pragma unroll
            for (int r = 0; r < 4; r++) z4[r] += kk[r];
        }
    }

    float* kvo = g_kv + (size_t)blk * Ee * Ee;
    #pragma unroll
    for (int r = 0; r < 4; r++) {
        float4 o; o.x = acc[r][0]; o.y = acc[r][1]; o.z = acc[r][2]; o.w = acc[r][3];
        *(float4*)&kvo[(e0 + r) * Ee + f0] = o;
    }
    if (tf == 0) {
        float* zo = g_zc + (size_t)blk * Ee;
        #pragma unroll
        for (int r = 0; r < 4; r++) zo[e0 + r] = z4[r];
    }
}

// ---------------------------------------------------------------------------
// Stage B: in-place exclusive prefix over the NC chunks of each (b,h).
// ---------------------------------------------------------------------------
__global__ __launch_bounds__(256)
void prefix_kv()
{
    const int bh = blockIdx.x;
    const int tid = threadIdx.x;
    float* kvb = g_kv + (size_t)bh * NC * Ee * Ee;

    #pragma unroll
    for (int t = 0; t < 16; t++) {
        const int idx = tid + t * 256;
        float run = 0.f;
        #pragma unroll
        for (int c = 0; c < NC; c++) {
            float tmp = kvb[(size_t)c * (Ee * Ee) + idx];
            kvb[(size_t)c * (Ee * Ee) + idx] = run;
            run += tmp;
        }
    }
    if (tid < Ee) {
        float* zb = g_zc + (size_t)bh * NC * Ee;
        float run = 0.f;
        #pragma unroll
        for (int c = 0; c < NC; c++) {
            float tmp = zb[c * Ee + tid];
            zb[c * Ee + tid] = run;
            run += tmp;
        }
    }
}

// ---------------------------------------------------------------------------
// Stage C: per-chunk attention. Epilogue writes bf16 hi/lo splits directly
// to g_ah / g_al (feeds the out-proj MMA).
// ---------------------------------------------------------------------------
#define CA_SQT 0                          // [64][132] Q transposed
#define CA_SKT (64 * 132)                 // [64][132] K transposed
#define CA_SV  (CA_SKT + 64 * 132)        // [128][68] V
#define CA_SA  (CA_SV + 128 * 68)         // [128][132] masked A
#define CA_SSP (CA_SA + 128 * 132)        // [64][68]  S_prev
#define CA_SZP (CA_SSP + 64 * 68)         // [64]      z_prev
#define CA_TOT ((CA_SZP + 64) * 4)        // bytes = 187648

__global__ __launch_bounds__(256)
void chunk_attn()
{
    extern __shared__ float s[];
    const int blk = blockIdx.x;
    const int bh = blk >> 4, c = blk & 15;
    const int b = bh >> 4, h = bh & 15;
    const size_t row0 = (size_t)b * Ll + c * CL;
    const float* qbase = g_qkv + row0 * TD + h * Ee;
    const float* kbase = qbase + Dd;
    const float* vbase = qbase + 2 * Dd;
    const int tid = threadIdx.x;

    // load Q,K transposed; V row-major
    #pragma unroll
    for (int t = 0; t < 8; t++) {
        int id = tid + t * 256;
        int i = id >> 4, e0 = (id & 15) * 4;
        float4 q4 = *(const float4*)(qbase + (size_t)i * TD + e0);
        float4 k4 = *(const float4*)(kbase + (size_t)i * TD + e0);
        float4 v4 = *(const float4*)(vbase + (size_t)i * TD + e0);
        s[CA_SQT + (e0 + 0) * 132 + i] = q4.x;
        s[CA_SQT + (e0 + 1) * 132 + i] = q4.y;
        s[CA_SQT + (e0 + 2) * 132 + i] = q4.z;
        s[CA_SQT + (e0 + 3) * 132 + i] = q4.w;
        s[CA_SKT + (e0 + 0) * 132 + i] = k4.x;
        s[CA_SKT + (e0 + 1) * 132 + i] = k4.y;
        s[CA_SKT + (e0 + 2) * 132 + i] = k4.z;
        s[CA_SKT + (e0 + 3) * 132 + i] = k4.w;
        *(float4*)&s[CA_SV + i * 68 + e0] = v4;
    }
    // load S_prev (exclusive prefix) and z_prev
    {
        const float* kvp = g_kv + (size_t)blk * (Ee * Ee);
        #pragma unroll
        for (int t = 0; t < 4; t++) {
            int id = tid + t * 256;          // 0..1023 = 64x16 float4
            int e = id >> 4, f0 = (id & 15) * 4;
            *(float4*)&s[CA_SSP + e * 68 + f0] = *(const float4*)(kvp + e * Ee + f0);
        }
        if (tid < Ee) s[CA_SZP + tid] = g_zc[(size_t)blk * Ee + tid];
    }
    __syncthreads();

    // Phase 1: masked A = Q K^T
    {
        const int ti = tid >> 4, tj = tid & 15;
        const int i0 = ti * 8, j0 = tj * 8;
        float acc[8][8] = {};
        for (int e = 0; e < Ee; e++) {
            float q8[8], k8[8];
            *(float4*)&q8[0] = *(float4*)&s[CA_SQT + e * 132 + i0];
            *(float4*)&q8[4] = *(float4*)&s[CA_SQT + e * 132 + i0 + 4];
            *(float4*)&k8[0] = *(float4*)&s[CA_SKT + e * 132 + j0];
            *(float4*)&k8[4] = *(float4*)&s[CA_SKT + e * 132 + j0 + 4];
            #pragma unroll
            for (int r = 0; r < 8; r++)
                #pragma unroll
                for (int t = 0; t < 8; t++)
                    acc[r][t] = fmaf(q8[r], k8[t], acc[r][t]);
        }
        #pragma unroll
        for (int r = 0; r < 8; r++)
            #pragma unroll
            for (int t = 0; t < 8; t++) {
                const int i = i0 + r, j = j0 + t;
                s[CA_SA + i * 132 + j] = (j <= i) ? acc[r][t] : 0.f;
            }
    }
    __syncthreads();

    // Phase 2: num = A V + Q S_prev ; den = rowsum(A) + q.z_prev
    {
        const int ti = tid >> 3, tf = tid & 7;
        const int i0 = ti * 4, f0 = tf * 8;
        float acc[4][8] = {};
        float den[4] = {0.f, 0.f, 0.f, 0.f};

        for (int j = 0; j < CL; j++) {
            float a4[4];
            #pragma unroll
            for (int r = 0; r < 4; r++) a4[r] = s[CA_SA + (i0 + r) * 132 + j];
            float v8[8];
            *(float4*)&v8[0] = *(float4*)&s[CA_SV + j * 68 + f0];
            *(float4*)&v8[4] = *(float4*)&s[CA_SV + j * 68 + f0 + 4];
            #pragma unroll
            for (int r = 0; r < 4; r++) {
                den[r] += a4[r];
                #pragma unroll
                for (int t = 0; t < 8; t++)
                    acc[r][t] = fmaf(a4[r], v8[t], acc[r][t]);
            }
        }
        for (int e = 0; e < Ee; e++) {
            float q4[4];
            #pragma unroll
            for (int r = 0; r < 4; r++) q4[r] = s[CA_SQT + e * 132 + i0 + r];
            float s8[8];
            *(float4*)&s8[0] = *(float4*)&s[CA_SSP + e * 68 + f0];
            *(float4*)&s8[4] = *(float4*)&s[CA_SSP + e * 68 + f0 + 4];
            const float zz = s[CA_SZP + e];
            #pragma unroll
            for (int r = 0; r < 4; r++) {
                den[r] = fmaf(q4[r], zz, den[r]);
                #pragma unroll
                for (int t = 0; t < 8; t++)
                    acc[r][t] = fmaf(q4[r], s8[t], acc[r][t]);
            }
        }
        #pragma unroll
        for (int r = 0; r < 4; r++) {
            const float inv = 1.f / (den[r] + 1e-4f);
            const size_t obase = (row0 + i0 + r) * Kdim + h * Ee + f0;
            __nv_bfloat16 hv[8], lv[8];
            #pragma unroll
            for (int t = 0; t < 8; t++) {
                const float v = acc[r][t] * inv;
                hv[t] = __float2bfloat16_rn(v);
                lv[t] = __float2bfloat16_rn(v - __bfloat162float(hv[t]));
            }
            *(uint4*)(g_ah + obase) = *(uint4*)hv;
            *(uint4*)(g_al + obase) = *(uint4*)lv;
        }
    }
}

// ---------------------------------------------------------------------------
// In-place LayerNorm over rows of d_out (4096 rows x 1024).
// ---------------------------------------------------------------------------
__global__ __launch_bounds__(256)
void layernorm_inplace(float* __restrict__ out,
                       const float* __restrict__ gamma,
                       const float* __restrict__ beta)
{
    const int row = blockIdx.x;
    float* p = out + (size_t)row * Dd;
    const int tid = threadIdx.x;

    float4 v = ((const float4*)p)[tid];
    float s = v.x + v.y + v.z + v.w;
    float q = v.x * v.x + v.y * v.y + v.z * v.z + v.w * v.w;

    #pragma unroll
    for (int o = 16; o > 0; o >>= 1) {
        s += __shfl_xor_sync(0xffffffffu, s, o);
        q += __shfl_xor_sync(0xffffffffu, q, o);
    }
    __shared__ float ss[8], sqr[8];
    const int w = tid >> 5, lane = tid & 31;
    if (lane == 0) { ss[w] = s; sqr[w] = q; }
    __syncthreads();
    if (w == 0) {
        s = (lane < 8) ? ss[lane] : 0.f;
        q = (lane < 8) ? sqr[lane] : 0.f;
        #pragma unroll
        for (int o = 4; o > 0; o >>= 1) {
            s += __shfl_xor_sync(0xffffffffu, s, o);
            q += __shfl_xor_sync(0xffffffffu, q, o);
        }
        if (lane == 0) { ss[0] = s; sqr[0] = q; }
    }
    __syncthreads();

    const float mu  = ss[0] * (1.f / 1024.f);
    const float var = sqr[0] * (1.f / 1024.f) - mu * mu;
    const float inv = rsqrtf(var + 1e-5f);

    float4 gv = ((const float4*)gamma)[tid];
    float4 bv = ((const float4*)beta)[tid];
    float4 o4;
    o4.x = (v.x - mu) * inv * gv.x + bv.x;
    o4.y = (v.y - mu) * inv * gv.y + bv.y;
    o4.z = (v.z - mu) * inv * gv.z + bv.z;
    o4.w = (v.w - mu) * inv * gv.w + bv.w;
    ((float4*)p)[tid] = o4;
}

// ---------------------------------------------------------------------------
extern "C" void kernel_launch(void* const* d_in, const int* in_sizes, int n_in,
                              void* d_out, int out_size)
{
    const float* x     = (const float*)d_in[0];
    const float* Wqkv  = (const float*)d_in[1];
    const float* bqkv  = (const float*)d_in[2];
    const float* Wout  = (const float*)d_in[3];
    const float* bout  = (const float*)d_in[4];
    const float* gamma = (const float*)d_in[5];
    const float* beta  = (const float*)d_in[6];
    float* out = (float*)d_out;

    cudaFuncSetAttribute(mma_gemm<true>,  cudaFuncAttributeMaxDynamicSharedMemorySize, GSM);
    cudaFuncSetAttribute(mma_gemm<false>, cudaFuncAttributeMaxDynamicSharedMemorySize, GSM);
    cudaFuncSetAttribute(chunk_kv,   cudaFuncAttributeMaxDynamicSharedMemorySize, CK_TOT);
    cudaFuncSetAttribute(chunk_attn, cudaFuncAttributeMaxDynamicSharedMemorySize, CA_TOT);

    __nv_bfloat16 *xh, *xl, *wqh, *wql, *woh, *wol;
    cudaGetSymbolAddress((void**)&xh,  g_xh);
    cudaGetSymbolAddress((void**)&xl,  g_xl);
    cudaGetSymbolAddress((void**)&wqh, g_wqh);
    cudaGetSymbolAddress((void**)&wql, g_wql);
    cudaGetSymbolAddress((void**)&woh, g_woh);
    cudaGetSymbolAddress((void**)&wol, g_wol);

    // 0) bf16 splits of x and weights
    split_bf16<<<(Mrows * Kdim / 4 + 255) / 256, 256>>>(x, xh, xl, Mrows * Kdim / 4);
    split_bf16<<<(TD * Kdim / 4 + 255) / 256, 256>>>(Wqkv, wqh, wql, TD * Kdim / 4);
    split_bf16<<<(Dd * Kdim / 4 + 255) / 256, 256>>>(Wout, woh, wol, Dd * Kdim / 4);

    // 1) QKV projection (mma.sync) + bias + feature maps -> g_qkv
    mma_gemm<true><<<dim3(TD / 128, Mrows / 128), 256, GSM>>>(bqkv, nullptr);

    // 2) Chunked causal linear attention -> g_ah/g_al (bf16 split, fused)
    chunk_kv<<<Bb * Hh * NC, 256, CK_TOT>>>();
    prefix_kv<<<Bb * Hh, 256>>>();
    chunk_attn<<<Bb * Hh * NC, 256, CA_TOT>>>();

    // 3) Output projection (mma.sync) + bias -> d_out
    mma_gemm<false><<<dim3(Dd / 128, Mrows / 128), 256, GSM>>>(bout, out);

    // 4) LayerNorm in place on d_out
    layernorm_inplace<<<Mrows, 256>>>(out, gamma, beta);
}